// round 2
// baseline (speedup 1.0000x reference)
#include <cuda_runtime.h>
#include <math.h>
#include <stdint.h>

// ---------------- problem constants ----------------
#define MB    8
#define NCC   512
#define NTOK  1024          // NC + NT
#define DMOD  256
#define NH    8
#define NLAY  6
#define FFD   1024
#define DHD   32
#define TOK   (MB * NTOK)   // 8192

// ---------------- device scratch (no allocations allowed) ----------------
__device__ float g_z[TOK * DMOD];        // residual stream
__device__ float g_h[TOK * DMOD];        // LN output
__device__ float g_qkv[TOK * 3 * DMOD];  // qkv projection
__device__ float g_att[TOK * DMOD];      // attention output
__device__ float g_ff[TOK * FFD];        // ff hidden

// ---------------- encoder: z = relu([x,y,flag]@W1+b1)@W2+b2 ----------------
__global__ __launch_bounds__(DMOD) void encode_kernel(
    const float* __restrict__ xc, const float* __restrict__ yc,
    const float* __restrict__ xt,
    const float* __restrict__ W1, const float* __restrict__ b1,
    const float* __restrict__ W2, const float* __restrict__ b2)
{
    int tok = blockIdx.x;          // 0..8191
    int m   = tok >> 10;
    int t   = tok & 1023;
    int d   = threadIdx.x;         // 0..255

    __shared__ float s_in[16];
    __shared__ float s_hid[DMOD];

    if (d < 10) {
        float v;
        if (d < 8) {
            v = (t < NCC) ? xc[(m * NCC + t) * 8 + d]
                          : xt[(m * NCC + (t - NCC)) * 8 + d];
        } else if (d == 8) {
            v = (t < NCC) ? yc[m * NCC + t] : 0.0f;
        } else {
            v = (t < NCC) ? 0.0f : 1.0f;
        }
        s_in[d] = v;
    }
    __syncthreads();

    float acc = b1[d];
    #pragma unroll
    for (int k = 0; k < 10; k++) acc += s_in[k] * W1[k * DMOD + d];
    s_hid[d] = fmaxf(acc, 0.0f);
    __syncthreads();

    float o = b2[d];
    for (int j = 0; j < DMOD; j++) o += s_hid[j] * W2[j * DMOD + d];
    g_z[(size_t)tok * DMOD + d] = o;
}

// ---------------- layernorm: y = (x-mu)*rstd*g + b ----------------
__global__ __launch_bounds__(DMOD) void ln_kernel(
    const float* __restrict__ x, const float* __restrict__ g,
    const float* __restrict__ b, float* __restrict__ y)
{
    int tok = blockIdx.x;
    int d   = threadIdx.x;
    __shared__ float red[DMOD];
    __shared__ float s_mu, s_rstd;

    float v = x[(size_t)tok * DMOD + d];
    red[d] = v;
    __syncthreads();
    #pragma unroll
    for (int s = 128; s > 0; s >>= 1) {
        if (d < s) red[d] += red[d + s];
        __syncthreads();
    }
    if (d == 0) s_mu = red[0] * (1.0f / DMOD);
    __syncthreads();
    float mu = s_mu;
    float dv = v - mu;
    red[d] = dv * dv;
    __syncthreads();
    #pragma unroll
    for (int s = 128; s > 0; s >>= 1) {
        if (d < s) red[d] += red[d + s];
        __syncthreads();
    }
    if (d == 0) s_rstd = rsqrtf(red[0] * (1.0f / DMOD) + 1e-5f);
    __syncthreads();
    y[(size_t)tok * DMOD + d] = dv * s_rstd * g[d] + b[d];
}

// ---------------- tiled SGEMM: C = A@W + bias (+relu) (+resid) ----------------
// A: [Mrows, K] row-major, W: [K, Ncols] row-major. BM=BN=128, BK=8, 8x8 micro.
template <bool RELU, bool RESID>
__global__ __launch_bounds__(256) void gemm_kernel(
    const float* __restrict__ A, const float* __restrict__ W,
    const float* __restrict__ bias, const float* __restrict__ Rsd,
    float* __restrict__ C, int K, int Ncols)
{
    const int BM = 128, BN = 128, BK = 8;
    __shared__ float As[BK][BM + 4];   // +4 keeps 16B alignment, kills conflicts
    __shared__ float Ws[BK][BN];

    int tid = threadIdx.x;
    int tx = tid & 15;        // 0..15 -> output cols
    int ty = tid >> 4;        // 0..15 -> output rows
    int row0 = blockIdx.y * BM;
    int col0 = blockIdx.x * BN;

    float acc[8][8];
    #pragma unroll
    for (int i = 0; i < 8; i++)
        #pragma unroll
        for (int j = 0; j < 8; j++) acc[i][j] = 0.0f;

    for (int k0 = 0; k0 < K; k0 += BK) {
        // A tile 128x8 (transposed into As)
        {
            int r  = tid >> 1;
            int cc = (tid & 1) * 4;
            float4 av = *(const float4*)(A + (size_t)(row0 + r) * K + k0 + cc);
            As[cc + 0][r] = av.x;
            As[cc + 1][r] = av.y;
            As[cc + 2][r] = av.z;
            As[cc + 3][r] = av.w;
        }
        // W tile 8x128
        {
            int r  = tid >> 5;
            int cc = (tid & 31) * 4;
            *(float4*)&Ws[r][cc] =
                *(const float4*)(W + (size_t)(k0 + r) * Ncols + col0 + cc);
        }
        __syncthreads();

        #pragma unroll
        for (int k = 0; k < BK; k++) {
            float a[8], w[8];
            *(float4*)&a[0] = *(const float4*)&As[k][ty * 8];
            *(float4*)&a[4] = *(const float4*)&As[k][ty * 8 + 4];
            *(float4*)&w[0] = *(const float4*)&Ws[k][tx * 8];
            *(float4*)&w[4] = *(const float4*)&Ws[k][tx * 8 + 4];
            #pragma unroll
            for (int i = 0; i < 8; i++)
                #pragma unroll
                for (int j = 0; j < 8; j++) acc[i][j] += a[i] * w[j];
        }
        __syncthreads();
    }

    #pragma unroll
    for (int i = 0; i < 8; i++) {
        int r = row0 + ty * 8 + i;
        #pragma unroll
        for (int j = 0; j < 8; j++) {
            int c = col0 + tx * 8 + j;
            float v = acc[i][j] + bias[c];
            if (RELU)  v = fmaxf(v, 0.0f);
            if (RESID) v += Rsd[(size_t)r * Ncols + c];
            C[(size_t)r * Ncols + c] = v;
        }
    }
}

// ---------------- masked flash attention ----------------
// Mask: context rows attend to the 512 context keys; target rows attend to
// 512 context keys + self. One thread per query row; K/V chunks staged in smem.
__global__ __launch_bounds__(256) void attn_kernel(
    const float* __restrict__ qkv, float* __restrict__ out)
{
    int mh   = blockIdx.x;                      // 0..63 = m*H + h
    int m    = mh >> 3;
    int h    = mh & 7;
    int qrow = blockIdx.y * 256 + threadIdx.x;  // 0..1023

    __shared__ float Ksh[128][DHD];
    __shared__ float Vsh[128][DHD];

    const float* base = qkv + (size_t)(m * NTOK) * (3 * DMOD);
    const float scale = 0.17677669529663687f;   // 1/sqrt(32)

    float q[DHD];
    {
        const float* qp = base + (size_t)qrow * (3 * DMOD) + h * DHD;
        #pragma unroll
        for (int d = 0; d < DHD; d++) q[d] = qp[d];
    }

    float mval = -INFINITY, ssum = 0.0f;
    float o[DHD];
    #pragma unroll
    for (int d = 0; d < DHD; d++) o[d] = 0.0f;

    for (int c = 0; c < 4; c++) {
        __syncthreads();
        for (int i = threadIdx.x; i < 128 * DHD; i += 256) {
            int kr = c * 128 + (i >> 5);
            int d  = i & 31;
            const float* kvb = base + (size_t)kr * (3 * DMOD) + h * DHD;
            Ksh[i >> 5][d] = kvb[DMOD + d];
            Vsh[i >> 5][d] = kvb[2 * DMOD + d];
        }
        __syncthreads();

        for (int j = 0; j < 128; j++) {
            float s = 0.0f;
            #pragma unroll
            for (int d = 0; d < DHD; d++) s += q[d] * Ksh[j][d];
            s *= scale;
            if (s > mval) {
                float corr = __expf(mval - s);
                ssum *= corr;
                #pragma unroll
                for (int d = 0; d < DHD; d++) o[d] *= corr;
                mval = s;
            }
            float p = __expf(s - mval);
            ssum += p;
            #pragma unroll
            for (int d = 0; d < DHD; d++) o[d] += p * Vsh[j][d];
        }
    }

    // self key for target rows
    if (qrow >= NCC) {
        const float* kp = base + (size_t)qrow * (3 * DMOD) + DMOD + h * DHD;
        const float* vp = kp + DMOD;
        float s = 0.0f;
        #pragma unroll
        for (int d = 0; d < DHD; d++) s += q[d] * kp[d];
        s *= scale;
        if (s > mval) {
            float corr = __expf(mval - s);
            ssum *= corr;
            #pragma unroll
            for (int d = 0; d < DHD; d++) o[d] *= corr;
            mval = s;
        }
        float p = __expf(s - mval);
        ssum += p;
        #pragma unroll
        for (int d = 0; d < DHD; d++) o[d] += p * vp[d];
    }

    float inv = 1.0f / ssum;
    float* op = out + (size_t)(m * NTOK + qrow) * DMOD + h * DHD;
    #pragma unroll
    for (int d = 0; d < DHD; d++) op[d] = o[d] * inv;
}

// ---------------- launch ----------------
extern "C" void kernel_launch(void* const* d_in, const int* in_sizes, int n_in,
                              void* d_out, int out_size)
{
    const float* xc     = (const float*)d_in[0];
    const float* yc     = (const float*)d_in[1];
    const float* xt     = (const float*)d_in[2];
    const float* enc_W1 = (const float*)d_in[3];
    const float* enc_b1 = (const float*)d_in[4];
    const float* enc_W2 = (const float*)d_in[5];
    const float* enc_b2 = (const float*)d_in[6];
    const float* Wqkv   = (const float*)d_in[7];
    const float* bqkv   = (const float*)d_in[8];
    const float* Wo     = (const float*)d_in[9];
    const float* bo     = (const float*)d_in[10];
    const float* ln1_g  = (const float*)d_in[11];
    const float* ln1_b  = (const float*)d_in[12];
    const float* ln2_g  = (const float*)d_in[13];
    const float* ln2_b  = (const float*)d_in[14];
    const float* Wff1   = (const float*)d_in[15];
    const float* bff1   = (const float*)d_in[16];
    const float* Wff2   = (const float*)d_in[17];
    const float* bff2   = (const float*)d_in[18];
    float* out          = (float*)d_out;

    float *z, *h, *qkv, *att, *ff;
    cudaGetSymbolAddress((void**)&z,   g_z);
    cudaGetSymbolAddress((void**)&h,   g_h);
    cudaGetSymbolAddress((void**)&qkv, g_qkv);
    cudaGetSymbolAddress((void**)&att, g_att);
    cudaGetSymbolAddress((void**)&ff,  g_ff);

    // encoder
    encode_kernel<<<TOK, DMOD>>>(xc, yc, xt, enc_W1, enc_b1, enc_W2, enc_b2);

    for (int l = 0; l < NLAY; l++) {
        const float* wqkv_l = Wqkv + (size_t)l * DMOD * 3 * DMOD;
        const float* bqkv_l = bqkv + (size_t)l * 3 * DMOD;
        const float* wo_l   = Wo   + (size_t)l * DMOD * DMOD;
        const float* bo_l   = bo   + (size_t)l * DMOD;
        const float* wff1_l = Wff1 + (size_t)l * DMOD * FFD;
        const float* bff1_l = bff1 + (size_t)l * FFD;
        const float* wff2_l = Wff2 + (size_t)l * FFD * DMOD;
        const float* bff2_l = bff2 + (size_t)l * DMOD;

        // h = LN1(z)
        ln_kernel<<<TOK, DMOD>>>(z, ln1_g + l * DMOD, ln1_b + l * DMOD, h);
        // qkv = h @ Wqkv + b
        gemm_kernel<false, false><<<dim3(3 * DMOD / 128, TOK / 128), 256>>>(
            h, wqkv_l, bqkv_l, nullptr, qkv, DMOD, 3 * DMOD);
        // att = softmax(qk^T * scale + mask) v
        attn_kernel<<<dim3(MB * NH, NTOK / 256), 256>>>(qkv, att);
        // z = z + att @ Wo + bo
        gemm_kernel<false, true><<<dim3(DMOD / 128, TOK / 128), 256>>>(
            att, wo_l, bo_l, z, z, DMOD, DMOD);
        // h = LN2(z)
        ln_kernel<<<TOK, DMOD>>>(z, ln2_g + l * DMOD, ln2_b + l * DMOD, h);
        // ff = relu(h @ Wff1 + b)
        gemm_kernel<true, false><<<dim3(FFD / 128, TOK / 128), 256>>>(
            h, wff1_l, bff1_l, nullptr, ff, DMOD, FFD);
        // z(out) = z + ff @ Wff2 + b ; last layer writes directly to d_out
        float* dst = (l == NLAY - 1) ? out : z;
        gemm_kernel<false, true><<<dim3(DMOD / 128, TOK / 128), 256>>>(
            ff, wff2_l, bff2_l, z, dst, FFD, DMOD);
    }
}

// round 4
// speedup vs baseline: 1.5151x; 1.5151x over previous
#include <cuda_runtime.h>
#include <math.h>
#include <stdint.h>

// ---------------- problem constants ----------------
#define MB    8
#define NCC   512
#define NTOK  1024
#define DMOD  256
#define NH    8
#define NLAY  6
#define FFD   1024
#define DHD   32
#define TOK   (MB * NTOK)   // 8192

// ---------------- device scratch ----------------
__device__ float g_z[TOK * DMOD];
__device__ float g_h[TOK * DMOD];
__device__ float g_qkv[TOK * 3 * DMOD];
__device__ float g_att[TOK * DMOD];
__device__ float g_ff[TOK * FFD];

// ---------------- cp.async helpers ----------------
__device__ __forceinline__ void cp_async16(void* dst, const void* src) {
    uint32_t d = (uint32_t)__cvta_generic_to_shared(dst);
    asm volatile("cp.async.cg.shared.global [%0], [%1], 16;\n" :: "r"(d), "l"(src));
}
__device__ __forceinline__ void cp_commit() { asm volatile("cp.async.commit_group;\n"); }
template <int N>
__device__ __forceinline__ void cp_wait() { asm volatile("cp.async.wait_group %0;\n" :: "n"(N)); }

// tf32 round-to-nearest helper
__device__ __forceinline__ uint32_t f2tf32(float x) {
    uint32_t r;
    asm("cvt.rna.tf32.f32 %0, %1;\n" : "=r"(r) : "f"(x));
    return r;
}

// ---------------- 3xTF32 tensor-core GEMM ----------------
// C[M,N] = A[M,K] @ W[K,N] + bias (+relu) (+resid). BM=BN=128, BK=16.
// 256 threads = 8 warps in 2x4 grid; warp tile 64x32; mma m16n8k8 tf32.
// Error-compensated: A,B split into tf32 hi+lo; acc += hh + hl + lh.
#define BM 128
#define BN 128
#define BKT 16
#define ASTR 20
#define BSTR 136

#define MMA_TF32(ACC, AF, BF)                                              \
    asm volatile(                                                          \
        "mma.sync.aligned.m16n8k8.row.col.f32.tf32.tf32.f32 "             \
        "{%0,%1,%2,%3}, {%4,%5,%6,%7}, {%8,%9}, {%0,%1,%2,%3};"           \
        : "+f"((ACC)[0]), "+f"((ACC)[1]), "+f"((ACC)[2]), "+f"((ACC)[3])  \
        : "r"((AF)[0]), "r"((AF)[1]), "r"((AF)[2]), "r"((AF)[3]),         \
          "r"((BF)[0]), "r"((BF)[1]))

template <bool RELU, bool RESID>
__global__ __launch_bounds__(256) void gemm_tc(
    const float* __restrict__ A, const float* __restrict__ W,
    const float* __restrict__ bias, const float* __restrict__ Rsd,
    float* __restrict__ C, int K, int N)
{
    __shared__ float As[2][BM * ASTR];
    __shared__ float Bs[2][BKT * BSTR];

    const int tid  = threadIdx.x;
    const int warp = tid >> 5, lane = tid & 31;
    const int g = lane >> 2, tg = lane & 3;
    const int wy = warp >> 2, wx = warp & 3;
    const int row0 = blockIdx.y * BM, col0 = blockIdx.x * BN;

    float acc[4][4][4];
    #pragma unroll
    for (int a = 0; a < 4; a++)
        #pragma unroll
        for (int b = 0; b < 4; b++)
            #pragma unroll
            for (int c = 0; c < 4; c++) acc[a][b][c] = 0.0f;

    const int ar0 = tid >> 2,         as0 = (tid & 3) * 4;
    const int ar1 = (tid + 256) >> 2, as1 = as0;
    const int br0 = tid >> 5,         bs0 = (tid & 31) * 4;
    const int br1 = (tid + 256) >> 5, bs1 = bs0;

    {
        cp_async16(&As[0][ar0 * ASTR + as0], A + (size_t)(row0 + ar0) * K + as0);
        cp_async16(&As[0][ar1 * ASTR + as1], A + (size_t)(row0 + ar1) * K + as1);
        cp_async16(&Bs[0][br0 * BSTR + bs0], W + (size_t)br0 * N + col0 + bs0);
        cp_async16(&Bs[0][br1 * BSTR + bs1], W + (size_t)br1 * N + col0 + bs1);
        cp_commit();
    }

    const int T = K / BKT;
    for (int t = 0; t < T; t++) {
        const int buf = t & 1;
        if (t + 1 < T) {
            const int k0 = (t + 1) * BKT;
            cp_async16(&As[buf ^ 1][ar0 * ASTR + as0], A + (size_t)(row0 + ar0) * K + k0 + as0);
            cp_async16(&As[buf ^ 1][ar1 * ASTR + as1], A + (size_t)(row0 + ar1) * K + k0 + as1);
            cp_async16(&Bs[buf ^ 1][br0 * BSTR + bs0], W + (size_t)(k0 + br0) * N + col0 + bs0);
            cp_async16(&Bs[buf ^ 1][br1 * BSTR + bs1], W + (size_t)(k0 + br1) * N + col0 + bs1);
            cp_commit();
            cp_wait<1>();
        } else {
            cp_wait<0>();
        }
        __syncthreads();

        #pragma unroll
        for (int kk = 0; kk < BKT; kk += 8) {
            uint32_t ah[4][4], al[4][4], bh[4][2], bl[4][2];
            #pragma unroll
            for (int mi = 0; mi < 4; mi++) {
                const float* p = &As[buf][(wy * 64 + mi * 16 + g) * ASTR + kk + tg];
                float v0 = p[0], v1 = p[8 * ASTR], v2 = p[4], v3 = p[8 * ASTR + 4];
                ah[mi][0] = f2tf32(v0);
                ah[mi][1] = f2tf32(v1);
                ah[mi][2] = f2tf32(v2);
                ah[mi][3] = f2tf32(v3);
                al[mi][0] = f2tf32(v0 - __uint_as_float(ah[mi][0]));
                al[mi][1] = f2tf32(v1 - __uint_as_float(ah[mi][1]));
                al[mi][2] = f2tf32(v2 - __uint_as_float(ah[mi][2]));
                al[mi][3] = f2tf32(v3 - __uint_as_float(ah[mi][3]));
            }
            #pragma unroll
            for (int ni = 0; ni < 4; ni++) {
                const float* p = &Bs[buf][(kk + tg) * BSTR + wx * 32 + ni * 8 + g];
                float v0 = p[0], v1 = p[4 * BSTR];
                bh[ni][0] = f2tf32(v0);
                bh[ni][1] = f2tf32(v1);
                bl[ni][0] = f2tf32(v0 - __uint_as_float(bh[ni][0]));
                bl[ni][1] = f2tf32(v1 - __uint_as_float(bh[ni][1]));
            }
            #pragma unroll
            for (int mi = 0; mi < 4; mi++)
                #pragma unroll
                for (int ni = 0; ni < 4; ni++) {
                    MMA_TF32(acc[mi][ni], al[mi], bh[ni]);   // lo*hi
                    MMA_TF32(acc[mi][ni], ah[mi], bl[ni]);   // hi*lo
                    MMA_TF32(acc[mi][ni], ah[mi], bh[ni]);   // hi*hi (last: largest term)
                }
        }
        __syncthreads();
    }

    // ---- epilogue ----
    #pragma unroll
    for (int mi = 0; mi < 4; mi++) {
        #pragma unroll
        for (int ni = 0; ni < 4; ni++) {
            const int r = row0 + wy * 64 + mi * 16 + g;
            const int c = col0 + wx * 32 + ni * 8 + tg * 2;
            const float b0 = bias[c], b1 = bias[c + 1];
            float v0 = acc[mi][ni][0] + b0;
            float v1 = acc[mi][ni][1] + b1;
            float v2 = acc[mi][ni][2] + b0;
            float v3 = acc[mi][ni][3] + b1;
            if (RELU) {
                v0 = fmaxf(v0, 0.0f); v1 = fmaxf(v1, 0.0f);
                v2 = fmaxf(v2, 0.0f); v3 = fmaxf(v3, 0.0f);
            }
            if (RESID) {
                v0 += Rsd[(size_t)r * N + c];
                v1 += Rsd[(size_t)r * N + c + 1];
                v2 += Rsd[(size_t)(r + 8) * N + c];
                v3 += Rsd[(size_t)(r + 8) * N + c + 1];
            }
            C[(size_t)r * N + c]           = v0;
            C[(size_t)r * N + c + 1]       = v1;
            C[(size_t)(r + 8) * N + c]     = v2;
            C[(size_t)(r + 8) * N + c + 1] = v3;
        }
    }
}

// ---------------- encoder layer-1: g_h = relu([x,y,flag]@W1 + b1) ----------------
__global__ __launch_bounds__(DMOD) void encode_hidden(
    const float* __restrict__ xc, const float* __restrict__ yc,
    const float* __restrict__ xt,
    const float* __restrict__ W1, const float* __restrict__ b1)
{
    int tok = blockIdx.x;
    int m = tok >> 10, t = tok & 1023;
    int d = threadIdx.x;

    __shared__ float s_in[16];
    if (d < 10) {
        float v;
        if (d < 8) {
            v = (t < NCC) ? xc[(m * NCC + t) * 8 + d]
                          : xt[(m * NCC + (t - NCC)) * 8 + d];
        } else if (d == 8) {
            v = (t < NCC) ? yc[m * NCC + t] : 0.0f;
        } else {
            v = (t < NCC) ? 0.0f : 1.0f;
        }
        s_in[d] = v;
    }
    __syncthreads();

    float acc = b1[d];
    #pragma unroll
    for (int k = 0; k < 10; k++) acc += s_in[k] * W1[k * DMOD + d];
    g_h[(size_t)tok * DMOD + d] = fmaxf(acc, 0.0f);
}

// ---------------- layernorm: warp-per-token ----------------
__global__ __launch_bounds__(256) void ln_kernel(
    const float* __restrict__ x, const float* __restrict__ g,
    const float* __restrict__ b, float* __restrict__ y)
{
    int tok  = (blockIdx.x * 256 + threadIdx.x) >> 5;
    int lane = threadIdx.x & 31;

    const float4* xp = (const float4*)(x + (size_t)tok * DMOD);
    float4 v0 = xp[lane * 2], v1 = xp[lane * 2 + 1];

    float s = v0.x + v0.y + v0.z + v0.w + v1.x + v1.y + v1.z + v1.w;
    #pragma unroll
    for (int o = 16; o > 0; o >>= 1) s += __shfl_xor_sync(0xffffffffu, s, o);
    float mu = s * (1.0f / DMOD);

    float d0 = v0.x - mu, d1 = v0.y - mu, d2 = v0.z - mu, d3 = v0.w - mu;
    float d4 = v1.x - mu, d5 = v1.y - mu, d6 = v1.z - mu, d7 = v1.w - mu;
    float q = d0*d0 + d1*d1 + d2*d2 + d3*d3 + d4*d4 + d5*d5 + d6*d6 + d7*d7;
    #pragma unroll
    for (int o = 16; o > 0; o >>= 1) q += __shfl_xor_sync(0xffffffffu, q, o);
    float rstd = rsqrtf(q * (1.0f / DMOD) + 1e-5f);

    const float4* gp = (const float4*)g;
    const float4* bp = (const float4*)b;
    float4 g0 = gp[lane * 2], g1 = gp[lane * 2 + 1];
    float4 b0 = bp[lane * 2], b1 = bp[lane * 2 + 1];

    float4 o0, o1;
    o0.x = d0 * rstd * g0.x + b0.x;  o0.y = d1 * rstd * g0.y + b0.y;
    o0.z = d2 * rstd * g0.z + b0.z;  o0.w = d3 * rstd * g0.w + b0.w;
    o1.x = d4 * rstd * g1.x + b1.x;  o1.y = d5 * rstd * g1.y + b1.y;
    o1.z = d6 * rstd * g1.z + b1.z;  o1.w = d7 * rstd * g1.w + b1.w;

    float4* yp = (float4*)(y + (size_t)tok * DMOD);
    yp[lane * 2] = o0;
    yp[lane * 2 + 1] = o1;
}

// ---------------- masked flash attention (float4 vectorized) ----------------
__global__ __launch_bounds__(256) void attn_kernel(
    const float* __restrict__ qkv, float* __restrict__ out)
{
    int mh   = blockIdx.x;
    int m    = mh >> 3;
    int h    = mh & 7;
    int qrow = blockIdx.y * 256 + threadIdx.x;

    __shared__ float4 Ksh[128][8];
    __shared__ float4 Vsh[128][8];

    const float* base = qkv + (size_t)(m * NTOK) * (3 * DMOD);
    const float scale = 0.17677669529663687f;  // 1/sqrt(32)

    float4 q[8];
    {
        const float4* qp = (const float4*)(base + (size_t)qrow * (3 * DMOD) + h * DHD);
        #pragma unroll
        for (int i = 0; i < 8; i++) q[i] = qp[i];
    }

    float mval = -INFINITY, ssum = 0.0f;
    float4 o[8];
    #pragma unroll
    for (int i = 0; i < 8; i++) o[i] = make_float4(0.f, 0.f, 0.f, 0.f);

    for (int c = 0; c < 4; c++) {
        __syncthreads();
        for (int i = threadIdx.x; i < 128 * 8; i += 256) {
            int kr = c * 128 + (i >> 3);
            int dd = i & 7;
            const float4* kp = (const float4*)(base + (size_t)kr * (3 * DMOD) + DMOD + h * DHD);
            const float4* vp = (const float4*)(base + (size_t)kr * (3 * DMOD) + 2 * DMOD + h * DHD);
            Ksh[i >> 3][dd] = kp[dd];
            Vsh[i >> 3][dd] = vp[dd];
        }
        __syncthreads();

        for (int j = 0; j < 128; j++) {
            float s = 0.0f;
            #pragma unroll
            for (int i = 0; i < 8; i++) {
                float4 kk = Ksh[j][i];
                s += q[i].x * kk.x + q[i].y * kk.y + q[i].z * kk.z + q[i].w * kk.w;
            }
            s *= scale;
            if (s > mval) {
                float corr = __expf(mval - s);
                ssum *= corr;
                #pragma unroll
                for (int i = 0; i < 8; i++) {
                    o[i].x *= corr; o[i].y *= corr; o[i].z *= corr; o[i].w *= corr;
                }
                mval = s;
            }
            float p = __expf(s - mval);
            ssum += p;
            #pragma unroll
            for (int i = 0; i < 8; i++) {
                float4 vv = Vsh[j][i];
                o[i].x += p * vv.x; o[i].y += p * vv.y;
                o[i].z += p * vv.z; o[i].w += p * vv.w;
            }
        }
    }

    // self key for target rows
    if (qrow >= NCC) {
        const float4* kp = (const float4*)(base + (size_t)qrow * (3 * DMOD) + DMOD + h * DHD);
        const float4* vp = (const float4*)(base + (size_t)qrow * (3 * DMOD) + 2 * DMOD + h * DHD);
        float s = 0.0f;
        #pragma unroll
        for (int i = 0; i < 8; i++) {
            float4 kk = kp[i];
            s += q[i].x * kk.x + q[i].y * kk.y + q[i].z * kk.z + q[i].w * kk.w;
        }
        s *= scale;
        if (s > mval) {
            float corr = __expf(mval - s);
            ssum *= corr;
            #pragma unroll
            for (int i = 0; i < 8; i++) {
                o[i].x *= corr; o[i].y *= corr; o[i].z *= corr; o[i].w *= corr;
            }
            mval = s;
        }
        float p = __expf(s - mval);
        ssum += p;
        #pragma unroll
        for (int i = 0; i < 8; i++) {
            float4 vv = vp[i];
            o[i].x += p * vv.x; o[i].y += p * vv.y;
            o[i].z += p * vv.z; o[i].w += p * vv.w;
        }
    }

    float inv = 1.0f / ssum;
    float4* op = (float4*)(out + (size_t)(m * NTOK + qrow) * DMOD + h * DHD);
    #pragma unroll
    for (int i = 0; i < 8; i++) {
        o[i].x *= inv; o[i].y *= inv; o[i].z *= inv; o[i].w *= inv;
        op[i] = o[i];
    }
}

// ---------------- launch ----------------
extern "C" void kernel_launch(void* const* d_in, const int* in_sizes, int n_in,
                              void* d_out, int out_size)
{
    const float* xc     = (const float*)d_in[0];
    const float* yc     = (const float*)d_in[1];
    const float* xt     = (const float*)d_in[2];
    const float* enc_W1 = (const float*)d_in[3];
    const float* enc_b1 = (const float*)d_in[4];
    const float* enc_W2 = (const float*)d_in[5];
    const float* enc_b2 = (const float*)d_in[6];
    const float* Wqkv   = (const float*)d_in[7];
    const float* bqkv   = (const float*)d_in[8];
    const float* Wo     = (const float*)d_in[9];
    const float* bo     = (const float*)d_in[10];
    const float* ln1_g  = (const float*)d_in[11];
    const float* ln1_b  = (const float*)d_in[12];
    const float* ln2_g  = (const float*)d_in[13];
    const float* ln2_b  = (const float*)d_in[14];
    const float* Wff1   = (const float*)d_in[15];
    const float* bff1   = (const float*)d_in[16];
    const float* Wff2   = (const float*)d_in[17];
    const float* bff2   = (const float*)d_in[18];
    float* out          = (float*)d_out;

    float *z, *h, *qkv, *att, *ff;
    cudaGetSymbolAddress((void**)&z,   g_z);
    cudaGetSymbolAddress((void**)&h,   g_h);
    cudaGetSymbolAddress((void**)&qkv, g_qkv);
    cudaGetSymbolAddress((void**)&att, g_att);
    cudaGetSymbolAddress((void**)&ff,  g_ff);

    // encoder: hidden then 3xTF32 GEMM for layer 2
    encode_hidden<<<TOK, DMOD>>>(xc, yc, xt, enc_W1, enc_b1);
    gemm_tc<false, false><<<dim3(DMOD / BN, TOK / BM), 256>>>(
        h, enc_W2, enc_b2, nullptr, z, DMOD, DMOD);

    for (int l = 0; l < NLAY; l++) {
        const float* wqkv_l = Wqkv + (size_t)l * DMOD * 3 * DMOD;
        const float* bqkv_l = bqkv + (size_t)l * 3 * DMOD;
        const float* wo_l   = Wo   + (size_t)l * DMOD * DMOD;
        const float* bo_l   = bo   + (size_t)l * DMOD;
        const float* wff1_l = Wff1 + (size_t)l * DMOD * FFD;
        const float* bff1_l = bff1 + (size_t)l * FFD;
        const float* wff2_l = Wff2 + (size_t)l * FFD * DMOD;
        const float* bff2_l = bff2 + (size_t)l * DMOD;

        ln_kernel<<<TOK / 8, 256>>>(z, ln1_g + l * DMOD, ln1_b + l * DMOD, h);
        gemm_tc<false, false><<<dim3(3 * DMOD / BN, TOK / BM), 256>>>(
            h, wqkv_l, bqkv_l, nullptr, qkv, DMOD, 3 * DMOD);
        attn_kernel<<<dim3(MB * NH, NTOK / 256), 256>>>(qkv, att);
        gemm_tc<false, true><<<dim3(DMOD / BN, TOK / BM), 256>>>(
            att, wo_l, bo_l, z, z, DMOD, DMOD);
        ln_kernel<<<TOK / 8, 256>>>(z, ln2_g + l * DMOD, ln2_b + l * DMOD, h);
        gemm_tc<true, false><<<dim3(FFD / BN, TOK / BM), 256>>>(
            h, wff1_l, bff1_l, nullptr, ff, DMOD, FFD);
        float* dst = (l == NLAY - 1) ? out : z;
        gemm_tc<false, true><<<dim3(DMOD / BN, TOK / BM), 256>>>(
            ff, wff2_l, bff2_l, z, dst, FFD, DMOD);
    }
}

// round 5
// speedup vs baseline: 1.8344x; 1.2107x over previous
#include <cuda_runtime.h>
#include <cuda_bf16.h>
#include <math.h>
#include <stdint.h>

// ---------------- problem constants ----------------
#define MB    8
#define NCC   512
#define NTOK  1024
#define DMOD  256
#define NH    8
#define NLAY  6
#define FFD   1024
#define DHD   32
#define TOK   (MB * NTOK)   // 8192

// ---------------- device scratch ----------------
__device__ float g_z[TOK * DMOD];
__device__ float g_h[TOK * DMOD];
__device__ float g_qkv[TOK * 3 * DMOD];
__device__ float g_att[TOK * DMOD];
__device__ float g_ff[TOK * FFD];

// ---------------- helpers ----------------
// pack two floats into bf16x2 (lo = k, hi = k+1)
__device__ __forceinline__ void split2(float x0, float x1, uint32_t& h, uint32_t& l) {
    uint32_t hh;
    asm("cvt.rn.bf16x2.f32 %0, %1, %2;" : "=r"(hh) : "f"(x1), "f"(x0));
    float h0f = __uint_as_float(hh << 16);          // lo half -> f32 (exact)
    float h1f = __uint_as_float(hh & 0xffff0000u);  // hi half -> f32 (exact)
    h = hh;
    float l0 = x0 - h0f, l1 = x1 - h1f;
    asm("cvt.rn.bf16x2.f32 %0, %1, %2;" : "=r"(l) : "f"(l1), "f"(l0));
}

#define LDM4(R0, R1, R2, R3, ADDR)                                          \
    asm volatile("ldmatrix.sync.aligned.m8n8.x4.shared.b16 {%0,%1,%2,%3}, [%4];" \
                 : "=r"(R0), "=r"(R1), "=r"(R2), "=r"(R3) : "r"(ADDR))

#define MMA_BF16(ACC, A0, A1, A2, A3, B0, B1)                               \
    asm volatile(                                                           \
        "mma.sync.aligned.m16n8k16.row.col.f32.bf16.bf16.f32 "             \
        "{%0,%1,%2,%3}, {%4,%5,%6,%7}, {%8,%9}, {%0,%1,%2,%3};"            \
        : "+f"((ACC)[0]), "+f"((ACC)[1]), "+f"((ACC)[2]), "+f"((ACC)[3])   \
        : "r"(A0), "r"(A1), "r"(A2), "r"(A3), "r"(B0), "r"(B1))

// ---------------- bf16x3 tensor-core GEMM ----------------
// C[M,N] = A[M,K] @ W[K,N] + bias (+relu) (+resid).
// BM=BN=128, BK=16. 8 warps (2x4), warp tile 64x32, mma m16n8k16 bf16.
// A,B split into bf16 hi+lo ONCE at tile load; acc += Al*Bh + Ah*Bl + Ah*Bh.
#define BM 128
#define BN 128
// smem row stride: 12 uint32 = 24 bf16 = 48B (conflict-free for ldmatrix)
#define RS 12

template <bool RELU, bool RESID>
__global__ __launch_bounds__(256) void gemm_tc(
    const float* __restrict__ A, const float* __restrict__ W,
    const float* __restrict__ bias, const float* __restrict__ Rsd,
    float* __restrict__ C, int K, int N)
{
    __shared__ uint32_t AsH[2][BM * RS];
    __shared__ uint32_t AsL[2][BM * RS];
    __shared__ uint32_t BsH[2][BN * RS];
    __shared__ uint32_t BsL[2][BN * RS];

    const int tid  = threadIdx.x;
    const int warp = tid >> 5, lane = tid & 31;
    const int g = lane >> 2, tg = lane & 3;
    const int wy = warp >> 2, wx = warp & 3;   // 2 x 4 warp grid
    const int row0 = blockIdx.y * BM, col0 = blockIdx.x * BN;

    float acc[4][4][4];
    #pragma unroll
    for (int a = 0; a < 4; a++)
        #pragma unroll
        for (int b = 0; b < 4; b++)
            #pragma unroll
            for (int c = 0; c < 4; c++) acc[a][b][c] = 0.0f;

    // ---- loader indices ----
    // A: 128x16 fp32 = 512 float4; thread handles f=tid and f=tid+256.
    const int arow0 = tid >> 2,         akq = tid & 3;       // k-quad (4 floats)
    const int arow1 = (tid + 256) >> 2;
    const float* Ap0 = A + (size_t)(row0 + arow0) * K + akq * 4;
    const float* Ap1 = A + (size_t)(row0 + arow1) * K + akq * 4;
    // B: 16x128 fp32, stored transposed (n-major) in smem.
    // thread: kp = k-pair 0..7, nq = n-quad 0..31
    const int kp = tid & 7, nq = tid >> 3;
    const float* Bp0 = W + (size_t)(2 * kp) * N + col0 + 4 * nq;

    // ---- ldmatrix per-lane byte offsets ----
    const int lm = lane >> 3, lr = lane & 7;
    const int frag_off = ((lm & 1) * 8 + lr) * (RS * 4) + (lm >> 1) * 16;
    const int a_woff = (wy * 64) * (RS * 4) + frag_off;
    const int b_woff = (wx * 32) * (RS * 4) + frag_off;

    float4 ra0, ra1, rb0, rb1;

    // stage loader
    auto load_regs = [&](int t) {
        ra0 = *(const float4*)(Ap0 + t * 16);
        ra1 = *(const float4*)(Ap1 + t * 16);
        rb0 = *(const float4*)(Bp0 + (size_t)t * 16 * N);
        rb1 = *(const float4*)(Bp0 + (size_t)t * 16 * N + N);
    };
    auto store_tile = [&](int b) {
        uint32_t h0, l0, h1, l1;
        split2(ra0.x, ra0.y, h0, l0);
        split2(ra0.z, ra0.w, h1, l1);
        *(uint2*)&AsH[b][arow0 * RS + akq * 2] = make_uint2(h0, h1);
        *(uint2*)&AsL[b][arow0 * RS + akq * 2] = make_uint2(l0, l1);
        split2(ra1.x, ra1.y, h0, l0);
        split2(ra1.z, ra1.w, h1, l1);
        *(uint2*)&AsH[b][arow1 * RS + akq * 2] = make_uint2(h0, h1);
        *(uint2*)&AsL[b][arow1 * RS + akq * 2] = make_uint2(l0, l1);
        // B transpose: pair (k, k+1) for each of 4 n values
        uint32_t h, l;
        split2(rb0.x, rb1.x, h, l);
        BsH[b][(4 * nq + 0) * RS + kp] = h;  BsL[b][(4 * nq + 0) * RS + kp] = l;
        split2(rb0.y, rb1.y, h, l);
        BsH[b][(4 * nq + 1) * RS + kp] = h;  BsL[b][(4 * nq + 1) * RS + kp] = l;
        split2(rb0.z, rb1.z, h, l);
        BsH[b][(4 * nq + 2) * RS + kp] = h;  BsL[b][(4 * nq + 2) * RS + kp] = l;
        split2(rb0.w, rb1.w, h, l);
        BsH[b][(4 * nq + 3) * RS + kp] = h;  BsL[b][(4 * nq + 3) * RS + kp] = l;
    };
    auto compute = [&](int b) {
        uint32_t aHb = (uint32_t)__cvta_generic_to_shared(&AsH[b][0]) + a_woff;
        uint32_t aLb = (uint32_t)__cvta_generic_to_shared(&AsL[b][0]) + a_woff;
        uint32_t bHb = (uint32_t)__cvta_generic_to_shared(&BsH[b][0]) + b_woff;
        uint32_t bLb = (uint32_t)__cvta_generic_to_shared(&BsL[b][0]) + b_woff;

        uint32_t bh[2][4], bl[2][4];
        #pragma unroll
        for (int p = 0; p < 2; p++) {
            LDM4(bh[p][0], bh[p][1], bh[p][2], bh[p][3], bHb + p * 16 * (RS * 4));
            LDM4(bl[p][0], bl[p][1], bl[p][2], bl[p][3], bLb + p * 16 * (RS * 4));
        }
        #pragma unroll
        for (int mi = 0; mi < 4; mi++) {
            uint32_t ah0, ah1, ah2, ah3, al0, al1, al2, al3;
            LDM4(ah0, ah1, ah2, ah3, aHb + mi * 16 * (RS * 4));
            LDM4(al0, al1, al2, al3, aLb + mi * 16 * (RS * 4));
            #pragma unroll
            for (int ni = 0; ni < 4; ni++) {
                const int p = ni >> 1, q = ni & 1;
                MMA_BF16(acc[mi][ni], al0, al1, al2, al3, bh[p][q], bh[p][q + 2]);
                MMA_BF16(acc[mi][ni], ah0, ah1, ah2, ah3, bl[p][q], bl[p][q + 2]);
                MMA_BF16(acc[mi][ni], ah0, ah1, ah2, ah3, bh[p][q], bh[p][q + 2]);
            }
        }
    };

    const int T = K / 16;
    load_regs(0);
    store_tile(0);
    if (T > 1) load_regs(1);
    __syncthreads();

    for (int t = 0; t < T; t++) {
        const int buf = t & 1;
        if (t + 1 < T) store_tile(buf ^ 1);
        if (t + 2 < T) load_regs(t + 2);
        compute(buf);
        __syncthreads();
    }

    // ---- epilogue ----
    #pragma unroll
    for (int mi = 0; mi < 4; mi++) {
        #pragma unroll
        for (int ni = 0; ni < 4; ni++) {
            const int r = row0 + wy * 64 + mi * 16 + g;
            const int c = col0 + wx * 32 + ni * 8 + tg * 2;
            const float b0 = bias[c], b1 = bias[c + 1];
            float v0 = acc[mi][ni][0] + b0;
            float v1 = acc[mi][ni][1] + b1;
            float v2 = acc[mi][ni][2] + b0;
            float v3 = acc[mi][ni][3] + b1;
            if (RELU) {
                v0 = fmaxf(v0, 0.0f); v1 = fmaxf(v1, 0.0f);
                v2 = fmaxf(v2, 0.0f); v3 = fmaxf(v3, 0.0f);
            }
            if (RESID) {
                v0 += Rsd[(size_t)r * N + c];
                v1 += Rsd[(size_t)r * N + c + 1];
                v2 += Rsd[(size_t)(r + 8) * N + c];
                v3 += Rsd[(size_t)(r + 8) * N + c + 1];
            }
            C[(size_t)r * N + c]           = v0;
            C[(size_t)r * N + c + 1]       = v1;
            C[(size_t)(r + 8) * N + c]     = v2;
            C[(size_t)(r + 8) * N + c + 1] = v3;
        }
    }
}

// ---------------- encoder layer-1: g_h = relu([x,y,flag]@W1 + b1) ----------------
__global__ __launch_bounds__(DMOD) void encode_hidden(
    const float* __restrict__ xc, const float* __restrict__ yc,
    const float* __restrict__ xt,
    const float* __restrict__ W1, const float* __restrict__ b1)
{
    int tok = blockIdx.x;
    int m = tok >> 10, t = tok & 1023;
    int d = threadIdx.x;

    __shared__ float s_in[16];
    if (d < 10) {
        float v;
        if (d < 8) {
            v = (t < NCC) ? xc[(m * NCC + t) * 8 + d]
                          : xt[(m * NCC + (t - NCC)) * 8 + d];
        } else if (d == 8) {
            v = (t < NCC) ? yc[m * NCC + t] : 0.0f;
        } else {
            v = (t < NCC) ? 0.0f : 1.0f;
        }
        s_in[d] = v;
    }
    __syncthreads();

    float acc = b1[d];
    #pragma unroll
    for (int k = 0; k < 10; k++) acc += s_in[k] * W1[k * DMOD + d];
    g_h[(size_t)tok * DMOD + d] = fmaxf(acc, 0.0f);
}

// ---------------- layernorm: warp-per-token ----------------
__global__ __launch_bounds__(256) void ln_kernel(
    const float* __restrict__ x, const float* __restrict__ g,
    const float* __restrict__ b, float* __restrict__ y)
{
    int tok  = (blockIdx.x * 256 + threadIdx.x) >> 5;
    int lane = threadIdx.x & 31;

    const float4* xp = (const float4*)(x + (size_t)tok * DMOD);
    float4 v0 = xp[lane * 2], v1 = xp[lane * 2 + 1];

    float s = v0.x + v0.y + v0.z + v0.w + v1.x + v1.y + v1.z + v1.w;
    #pragma unroll
    for (int o = 16; o > 0; o >>= 1) s += __shfl_xor_sync(0xffffffffu, s, o);
    float mu = s * (1.0f / DMOD);

    float d0 = v0.x - mu, d1 = v0.y - mu, d2 = v0.z - mu, d3 = v0.w - mu;
    float d4 = v1.x - mu, d5 = v1.y - mu, d6 = v1.z - mu, d7 = v1.w - mu;
    float q = d0*d0 + d1*d1 + d2*d2 + d3*d3 + d4*d4 + d5*d5 + d6*d6 + d7*d7;
    #pragma unroll
    for (int o = 16; o > 0; o >>= 1) q += __shfl_xor_sync(0xffffffffu, q, o);
    float rstd = rsqrtf(q * (1.0f / DMOD) + 1e-5f);

    const float4* gp = (const float4*)g;
    const float4* bp = (const float4*)b;
    float4 g0 = gp[lane * 2], g1 = gp[lane * 2 + 1];
    float4 b0 = bp[lane * 2], b1 = bp[lane * 2 + 1];

    float4 o0, o1;
    o0.x = d0 * rstd * g0.x + b0.x;  o0.y = d1 * rstd * g0.y + b0.y;
    o0.z = d2 * rstd * g0.z + b0.z;  o0.w = d3 * rstd * g0.w + b0.w;
    o1.x = d4 * rstd * g1.x + b1.x;  o1.y = d5 * rstd * g1.y + b1.y;
    o1.z = d6 * rstd * g1.z + b1.z;  o1.w = d7 * rstd * g1.w + b1.w;

    float4* yp = (float4*)(y + (size_t)tok * DMOD);
    yp[lane * 2] = o0;
    yp[lane * 2 + 1] = o1;
}

// ---------------- masked flash attention (float4 vectorized) ----------------
__global__ __launch_bounds__(256) void attn_kernel(
    const float* __restrict__ qkv, float* __restrict__ out)
{
    int mh   = blockIdx.x;
    int m    = mh >> 3;
    int h    = mh & 7;
    int qrow = blockIdx.y * 256 + threadIdx.x;

    __shared__ float4 Ksh[128][8];
    __shared__ float4 Vsh[128][8];

    const float* base = qkv + (size_t)(m * NTOK) * (3 * DMOD);
    const float scale = 0.17677669529663687f;  // 1/sqrt(32)

    float4 q[8];
    {
        const float4* qp = (const float4*)(base + (size_t)qrow * (3 * DMOD) + h * DHD);
        #pragma unroll
        for (int i = 0; i < 8; i++) q[i] = qp[i];
    }

    float mval = -INFINITY, ssum = 0.0f;
    float4 o[8];
    #pragma unroll
    for (int i = 0; i < 8; i++) o[i] = make_float4(0.f, 0.f, 0.f, 0.f);

    for (int c = 0; c < 4; c++) {
        __syncthreads();
        for (int i = threadIdx.x; i < 128 * 8; i += 256) {
            int kr = c * 128 + (i >> 3);
            int dd = i & 7;
            const float4* kp = (const float4*)(base + (size_t)kr * (3 * DMOD) + DMOD + h * DHD);
            const float4* vp = (const float4*)(base + (size_t)kr * (3 * DMOD) + 2 * DMOD + h * DHD);
            Ksh[i >> 3][dd] = kp[dd];
            Vsh[i >> 3][dd] = vp[dd];
        }
        __syncthreads();

        for (int j = 0; j < 128; j++) {
            float s = 0.0f;
            #pragma unroll
            for (int i = 0; i < 8; i++) {
                float4 kk = Ksh[j][i];
                s += q[i].x * kk.x + q[i].y * kk.y + q[i].z * kk.z + q[i].w * kk.w;
            }
            s *= scale;
            if (s > mval) {
                float corr = __expf(mval - s);
                ssum *= corr;
                #pragma unroll
                for (int i = 0; i < 8; i++) {
                    o[i].x *= corr; o[i].y *= corr; o[i].z *= corr; o[i].w *= corr;
                }
                mval = s;
            }
            float p = __expf(s - mval);
            ssum += p;
            #pragma unroll
            for (int i = 0; i < 8; i++) {
                float4 vv = Vsh[j][i];
                o[i].x += p * vv.x; o[i].y += p * vv.y;
                o[i].z += p * vv.z; o[i].w += p * vv.w;
            }
        }
    }

    // self key for target rows
    if (qrow >= NCC) {
        const float4* kp = (const float4*)(base + (size_t)qrow * (3 * DMOD) + DMOD + h * DHD);
        const float4* vp = (const float4*)(base + (size_t)qrow * (3 * DMOD) + 2 * DMOD + h * DHD);
        float s = 0.0f;
        #pragma unroll
        for (int i = 0; i < 8; i++) {
            float4 kk = kp[i];
            s += q[i].x * kk.x + q[i].y * kk.y + q[i].z * kk.z + q[i].w * kk.w;
        }
        s *= scale;
        if (s > mval) {
            float corr = __expf(mval - s);
            ssum *= corr;
            #pragma unroll
            for (int i = 0; i < 8; i++) {
                o[i].x *= corr; o[i].y *= corr; o[i].z *= corr; o[i].w *= corr;
            }
            mval = s;
        }
        float p = __expf(s - mval);
        ssum += p;
        #pragma unroll
        for (int i = 0; i < 8; i++) {
            float4 vv = vp[i];
            o[i].x += p * vv.x; o[i].y += p * vv.y;
            o[i].z += p * vv.z; o[i].w += p * vv.w;
        }
    }

    float inv = 1.0f / ssum;
    float4* op = (float4*)(out + (size_t)(m * NTOK + qrow) * DMOD + h * DHD);
    #pragma unroll
    for (int i = 0; i < 8; i++) {
        o[i].x *= inv; o[i].y *= inv; o[i].z *= inv; o[i].w *= inv;
        op[i] = o[i];
    }
}

// ---------------- launch ----------------
extern "C" void kernel_launch(void* const* d_in, const int* in_sizes, int n_in,
                              void* d_out, int out_size)
{
    const float* xc     = (const float*)d_in[0];
    const float* yc     = (const float*)d_in[1];
    const float* xt     = (const float*)d_in[2];
    const float* enc_W1 = (const float*)d_in[3];
    const float* enc_b1 = (const float*)d_in[4];
    const float* enc_W2 = (const float*)d_in[5];
    const float* enc_b2 = (const float*)d_in[6];
    const float* Wqkv   = (const float*)d_in[7];
    const float* bqkv   = (const float*)d_in[8];
    const float* Wo     = (const float*)d_in[9];
    const float* bo     = (const float*)d_in[10];
    const float* ln1_g  = (const float*)d_in[11];
    const float* ln1_b  = (const float*)d_in[12];
    const float* ln2_g  = (const float*)d_in[13];
    const float* ln2_b  = (const float*)d_in[14];
    const float* Wff1   = (const float*)d_in[15];
    const float* bff1   = (const float*)d_in[16];
    const float* Wff2   = (const float*)d_in[17];
    const float* bff2   = (const float*)d_in[18];
    float* out          = (float*)d_out;

    float *z, *h, *qkv, *att, *ff;
    cudaGetSymbolAddress((void**)&z,   g_z);
    cudaGetSymbolAddress((void**)&h,   g_h);
    cudaGetSymbolAddress((void**)&qkv, g_qkv);
    cudaGetSymbolAddress((void**)&att, g_att);
    cudaGetSymbolAddress((void**)&ff,  g_ff);

    // encoder: hidden then bf16x3 GEMM for layer 2
    encode_hidden<<<TOK, DMOD>>>(xc, yc, xt, enc_W1, enc_b1);
    gemm_tc<false, false><<<dim3(DMOD / BN, TOK / BM), 256>>>(
        h, enc_W2, enc_b2, nullptr, z, DMOD, DMOD);

    for (int l = 0; l < NLAY; l++) {
        const float* wqkv_l = Wqkv + (size_t)l * DMOD * 3 * DMOD;
        const float* bqkv_l = bqkv + (size_t)l * 3 * DMOD;
        const float* wo_l   = Wo   + (size_t)l * DMOD * DMOD;
        const float* bo_l   = bo   + (size_t)l * DMOD;
        const float* wff1_l = Wff1 + (size_t)l * DMOD * FFD;
        const float* bff1_l = bff1 + (size_t)l * FFD;
        const float* wff2_l = Wff2 + (size_t)l * FFD * DMOD;
        const float* bff2_l = bff2 + (size_t)l * DMOD;

        ln_kernel<<<TOK / 8, 256>>>(z, ln1_g + l * DMOD, ln1_b + l * DMOD, h);
        gemm_tc<false, false><<<dim3(3 * DMOD / BN, TOK / BM), 256>>>(
            h, wqkv_l, bqkv_l, nullptr, qkv, DMOD, 3 * DMOD);
        attn_kernel<<<dim3(MB * NH, NTOK / 256), 256>>>(qkv, att);
        gemm_tc<false, true><<<dim3(DMOD / BN, TOK / BM), 256>>>(
            att, wo_l, bo_l, z, z, DMOD, DMOD);
        ln_kernel<<<TOK / 8, 256>>>(z, ln2_g + l * DMOD, ln2_b + l * DMOD, h);
        gemm_tc<true, false><<<dim3(FFD / BN, TOK / BM), 256>>>(
            h, wff1_l, bff1_l, nullptr, ff, DMOD, FFD);
        float* dst = (l == NLAY - 1) ? out : z;
        gemm_tc<false, true><<<dim3(DMOD / BN, TOK / BM), 256>>>(
            ff, wff2_l, bff2_l, z, dst, FFD, DMOD);
    }
}

// round 6
// speedup vs baseline: 1.8574x; 1.0126x over previous
#include <cuda_runtime.h>
#include <cuda_bf16.h>
#include <math.h>
#include <stdint.h>

// ---------------- problem constants ----------------
#define MB    8
#define NCC   512
#define NTOK  1024
#define DMOD  256
#define NH    8
#define NLAY  6
#define FFD   1024
#define DHD   32
#define TOK   (MB * NTOK)   // 8192

// ---------------- device scratch ----------------
__device__ float g_z[TOK * DMOD];
__device__ float g_qkv[TOK * 3 * DMOD];
// split activations (bf16 hi/lo packed as uint32 pairs)
__device__ uint32_t g_h_h[TOK * DMOD / 2],  g_h_l[TOK * DMOD / 2];
__device__ uint32_t g_att_h[TOK * DMOD / 2], g_att_l[TOK * DMOD / 2];
__device__ uint32_t g_ff_h[TOK * FFD / 2],   g_ff_l[TOK * FFD / 2];
// split weights
__device__ uint32_t g_wqkv_h[NLAY * DMOD * 3 * DMOD / 2], g_wqkv_l[NLAY * DMOD * 3 * DMOD / 2];
__device__ uint32_t g_wo_h[NLAY * DMOD * DMOD / 2],       g_wo_l[NLAY * DMOD * DMOD / 2];
__device__ uint32_t g_wff1_h[NLAY * DMOD * FFD / 2],      g_wff1_l[NLAY * DMOD * FFD / 2];
__device__ uint32_t g_wff2_h[NLAY * FFD * DMOD / 2],      g_wff2_l[NLAY * FFD * DMOD / 2];
__device__ uint32_t g_ew2_h[DMOD * DMOD / 2],             g_ew2_l[DMOD * DMOD / 2];

// ---------------- helpers ----------------
__device__ __forceinline__ void split2(float x0, float x1, uint32_t& h, uint32_t& l) {
    uint32_t hh;
    asm("cvt.rn.bf16x2.f32 %0, %1, %2;" : "=r"(hh) : "f"(x1), "f"(x0));
    float h0f = __uint_as_float(hh << 16);
    float h1f = __uint_as_float(hh & 0xffff0000u);
    h = hh;
    float l0 = x0 - h0f, l1 = x1 - h1f;
    asm("cvt.rn.bf16x2.f32 %0, %1, %2;" : "=r"(l) : "f"(l1), "f"(l0));
}

__device__ __forceinline__ void cp_async16(void* dst, const void* src) {
    uint32_t d = (uint32_t)__cvta_generic_to_shared(dst);
    asm volatile("cp.async.cg.shared.global [%0], [%1], 16;\n" :: "r"(d), "l"(src));
}
__device__ __forceinline__ void cp_commit() { asm volatile("cp.async.commit_group;\n"); }
template <int N>
__device__ __forceinline__ void cp_wait() { asm volatile("cp.async.wait_group %0;\n" :: "n"(N)); }

#define LDM4(R0, R1, R2, R3, ADDR)                                          \
    asm volatile("ldmatrix.sync.aligned.m8n8.x4.shared.b16 {%0,%1,%2,%3}, [%4];" \
                 : "=r"(R0), "=r"(R1), "=r"(R2), "=r"(R3) : "r"(ADDR))

#define LDM4T(R0, R1, R2, R3, ADDR)                                         \
    asm volatile("ldmatrix.sync.aligned.m8n8.x4.trans.shared.b16 {%0,%1,%2,%3}, [%4];" \
                 : "=r"(R0), "=r"(R1), "=r"(R2), "=r"(R3) : "r"(ADDR))

#define MMA_BF16(ACC, A0, A1, A2, A3, B0, B1)                               \
    asm volatile(                                                           \
        "mma.sync.aligned.m16n8k16.row.col.f32.bf16.bf16.f32 "             \
        "{%0,%1,%2,%3}, {%4,%5,%6,%7}, {%8,%9}, {%0,%1,%2,%3};"            \
        : "+f"((ACC)[0]), "+f"((ACC)[1]), "+f"((ACC)[2]), "+f"((ACC)[3])   \
        : "r"(A0), "r"(A1), "r"(A2), "r"(A3), "r"(B0), "r"(B1))

// ---------------- weight split: fp32 -> bf16 hi/lo ----------------
__global__ void split_kernel(const float* __restrict__ src,
                             uint32_t* __restrict__ hi, uint32_t* __restrict__ lo,
                             int npairs)
{
    int i = blockIdx.x * 256 + threadIdx.x;
    if (i < npairs) {
        uint32_t h, l;
        split2(src[2 * i], src[2 * i + 1], h, l);
        hi[i] = h;
        lo[i] = l;
    }
}

// ---------------- pure-bf16 3-pass tensor-core GEMM ----------------
// C[M,N] = (Ah+Al)@(Bh+Bl) + bias, 3 passes (AlBh + AhBl + AhBh).
// BM=128, BN=128, BK=32. 4 warps (2x2), warp tile 64x64.
#define BM 128
#define BN 128
#define BK 32
#define AST 40    // A smem row stride (bf16): 32 + 8 pad -> 80B rows
#define BST 136   // B smem row stride (bf16): 128 + 8 pad -> 272B rows
#define GEMM_SMEM (2*BM*AST*2*2 + 2*BK*BST*2*2)   // 75776 bytes

// OUTMODE: 0 = fp32, 1 = fp32 + residual, 2 = relu + bf16 hi/lo split
template <int OUTMODE>
__global__ __launch_bounds__(128) void gemm_bf3(
    const __nv_bfloat16* __restrict__ Ah, const __nv_bfloat16* __restrict__ Al,
    const __nv_bfloat16* __restrict__ Bh, const __nv_bfloat16* __restrict__ Bl,
    const float* __restrict__ bias, const float* __restrict__ Rsd,
    float* __restrict__ C, uint32_t* __restrict__ Chi, uint32_t* __restrict__ Clo,
    int K, int N)
{
    extern __shared__ char smem_raw[];
    __nv_bfloat16* sAh = (__nv_bfloat16*)smem_raw;
    __nv_bfloat16* sAl = sAh + 2 * BM * AST;
    __nv_bfloat16* sBh = sAl + 2 * BM * AST;
    __nv_bfloat16* sBl = sBh + 2 * BK * BST;

    const int tid = threadIdx.x;
    const int warp = tid >> 5, lane = tid & 31;
    const int g = lane >> 2, tg = lane & 3;
    const int wy = warp >> 1, wx = warp & 1;   // 2x2 warps, warp tile 64x64
    const int row0 = blockIdx.y * BM, col0 = blockIdx.x * BN;

    float acc[4][8][4];
    #pragma unroll
    for (int a = 0; a < 4; a++)
        #pragma unroll
        for (int b = 0; b < 8; b++)
            #pragma unroll
            for (int c = 0; c < 4; c++) acc[a][b][c] = 0.0f;

    // loader indices
    const int brow = tid >> 2, bc0 = (tid & 3) * 32;   // B: 32 rows x 128 cols

    auto issue = [&](int t, int b) {
        const __nv_bfloat16* aH = Ah + (size_t)(row0 + tid) * K + t * BK;
        const __nv_bfloat16* aL = Al + (size_t)(row0 + tid) * K + t * BK;
        __nv_bfloat16* dAh = sAh + b * BM * AST + tid * AST;
        __nv_bfloat16* dAl = sAl + b * BM * AST + tid * AST;
        #pragma unroll
        for (int c = 0; c < 4; c++) {
            cp_async16(dAh + c * 8, aH + c * 8);
            cp_async16(dAl + c * 8, aL + c * 8);
        }
        const __nv_bfloat16* bH = Bh + (size_t)(t * BK + brow) * N + col0 + bc0;
        const __nv_bfloat16* bL = Bl + (size_t)(t * BK + brow) * N + col0 + bc0;
        __nv_bfloat16* dBh = sBh + b * BK * BST + brow * BST + bc0;
        __nv_bfloat16* dBl = sBl + b * BK * BST + brow * BST + bc0;
        #pragma unroll
        for (int c = 0; c < 4; c++) {
            cp_async16(dBh + c * 8, bH + c * 8);
            cp_async16(dBl + c * 8, bL + c * 8);
        }
        cp_commit();
    };

    // ldmatrix lane addressing
    const int a_lane = (wy * 64 + (lane & 15)) * (AST * 2) + (lane >> 4) * 16;
    const int b_lane = (lane & 15) * (BST * 2) + (lane >> 4) * 16 + wx * 128;

    auto compute = [&](int b) {
        uint32_t aHb = (uint32_t)__cvta_generic_to_shared(sAh + b * BM * AST) + a_lane;
        uint32_t aLb = (uint32_t)__cvta_generic_to_shared(sAl + b * BM * AST) + a_lane;
        uint32_t bHb = (uint32_t)__cvta_generic_to_shared(sBh + b * BK * BST) + b_lane;
        uint32_t bLb = (uint32_t)__cvta_generic_to_shared(sBl + b * BK * BST) + b_lane;

        #pragma unroll
        for (int ks = 0; ks < 2; ks++) {
            uint32_t ah[4][4], al[4][4];
            #pragma unroll
            for (int mi = 0; mi < 4; mi++) {
                LDM4(ah[mi][0], ah[mi][1], ah[mi][2], ah[mi][3],
                     aHb + mi * 16 * (AST * 2) + ks * 32);
                LDM4(al[mi][0], al[mi][1], al[mi][2], al[mi][3],
                     aLb + mi * 16 * (AST * 2) + ks * 32);
            }
            #pragma unroll
            for (int nc = 0; nc < 4; nc++) {
                uint32_t bh0, bh1, bh2, bh3, bl0, bl1, bl2, bl3;
                LDM4T(bh0, bh1, bh2, bh3, bHb + ks * 16 * (BST * 2) + nc * 32);
                LDM4T(bl0, bl1, bl2, bl3, bLb + ks * 16 * (BST * 2) + nc * 32);
                // pass 1: Al * Bh
                #pragma unroll
                for (int mi = 0; mi < 4; mi++) {
                    MMA_BF16(acc[mi][nc * 2],     al[mi][0], al[mi][1], al[mi][2], al[mi][3], bh0, bh1);
                    MMA_BF16(acc[mi][nc * 2 + 1], al[mi][0], al[mi][1], al[mi][2], al[mi][3], bh2, bh3);
                }
                // pass 2: Ah * Bl
                #pragma unroll
                for (int mi = 0; mi < 4; mi++) {
                    MMA_BF16(acc[mi][nc * 2],     ah[mi][0], ah[mi][1], ah[mi][2], ah[mi][3], bl0, bl1);
                    MMA_BF16(acc[mi][nc * 2 + 1], ah[mi][0], ah[mi][1], ah[mi][2], ah[mi][3], bl2, bl3);
                }
                // pass 3: Ah * Bh
                #pragma unroll
                for (int mi = 0; mi < 4; mi++) {
                    MMA_BF16(acc[mi][nc * 2],     ah[mi][0], ah[mi][1], ah[mi][2], ah[mi][3], bh0, bh1);
                    MMA_BF16(acc[mi][nc * 2 + 1], ah[mi][0], ah[mi][1], ah[mi][2], ah[mi][3], bh2, bh3);
                }
            }
        }
    };

    const int T = K / BK;
    issue(0, 0);
    for (int t = 0; t < T; t++) {
        const int buf = t & 1;
        if (t + 1 < T) {
            issue(t + 1, buf ^ 1);
            cp_wait<1>();
        } else {
            cp_wait<0>();
        }
        __syncthreads();
        compute(buf);
        __syncthreads();
    }

    // ---- epilogue ----
    #pragma unroll
    for (int mi = 0; mi < 4; mi++) {
        #pragma unroll
        for (int ni = 0; ni < 8; ni++) {
            const int r = row0 + wy * 64 + mi * 16 + g;
            const int c = col0 + wx * 64 + ni * 8 + tg * 2;
            const float b0 = bias[c], b1 = bias[c + 1];
            float v0 = acc[mi][ni][0] + b0;
            float v1 = acc[mi][ni][1] + b1;
            float v2 = acc[mi][ni][2] + b0;
            float v3 = acc[mi][ni][3] + b1;
            if (OUTMODE == 2) {
                v0 = fmaxf(v0, 0.0f); v1 = fmaxf(v1, 0.0f);
                v2 = fmaxf(v2, 0.0f); v3 = fmaxf(v3, 0.0f);
                uint32_t h, l;
                split2(v0, v1, h, l);
                Chi[((size_t)r * N + c) >> 1] = h;
                Clo[((size_t)r * N + c) >> 1] = l;
                split2(v2, v3, h, l);
                Chi[((size_t)(r + 8) * N + c) >> 1] = h;
                Clo[((size_t)(r + 8) * N + c) >> 1] = l;
            } else {
                if (OUTMODE == 1) {
                    v0 += Rsd[(size_t)r * N + c];
                    v1 += Rsd[(size_t)r * N + c + 1];
                    v2 += Rsd[(size_t)(r + 8) * N + c];
                    v3 += Rsd[(size_t)(r + 8) * N + c + 1];
                }
                *(float2*)&C[(size_t)r * N + c]       = make_float2(v0, v1);
                *(float2*)&C[(size_t)(r + 8) * N + c] = make_float2(v2, v3);
            }
        }
    }
}

// ---------------- encoder layer-1: hid = relu([x,y,flag]@W1 + b1) -> hi/lo ----------------
__global__ __launch_bounds__(128) void encode_hidden(
    const float* __restrict__ xc, const float* __restrict__ yc,
    const float* __restrict__ xt,
    const float* __restrict__ W1, const float* __restrict__ b1,
    uint32_t* __restrict__ hh, uint32_t* __restrict__ hl)
{
    int tok = blockIdx.x;
    int m = tok >> 10, t = tok & 1023;
    int tid = threadIdx.x;
    int d = tid * 2;

    __shared__ float s_in[16];
    if (tid < 10) {
        float v;
        if (tid < 8) {
            v = (t < NCC) ? xc[(m * NCC + t) * 8 + tid]
                          : xt[(m * NCC + (t - NCC)) * 8 + tid];
        } else if (tid == 8) {
            v = (t < NCC) ? yc[m * NCC + t] : 0.0f;
        } else {
            v = (t < NCC) ? 0.0f : 1.0f;
        }
        s_in[tid] = v;
    }
    __syncthreads();

    float a0 = b1[d], a1 = b1[d + 1];
    #pragma unroll
    for (int k = 0; k < 10; k++) {
        a0 += s_in[k] * W1[k * DMOD + d];
        a1 += s_in[k] * W1[k * DMOD + d + 1];
    }
    uint32_t h, l;
    split2(fmaxf(a0, 0.0f), fmaxf(a1, 0.0f), h, l);
    hh[tok * 128 + tid] = h;
    hl[tok * 128 + tid] = l;
}

// ---------------- layernorm: warp-per-token, bf16 hi/lo output ----------------
__global__ __launch_bounds__(256) void ln_kernel(
    const float* __restrict__ x, const float* __restrict__ g,
    const float* __restrict__ b,
    uint32_t* __restrict__ yh, uint32_t* __restrict__ yl)
{
    int tok  = (blockIdx.x * 256 + threadIdx.x) >> 5;
    int lane = threadIdx.x & 31;

    const float4* xp = (const float4*)(x + (size_t)tok * DMOD);
    float4 v0 = xp[lane * 2], v1 = xp[lane * 2 + 1];

    float s = v0.x + v0.y + v0.z + v0.w + v1.x + v1.y + v1.z + v1.w;
    #pragma unroll
    for (int o = 16; o > 0; o >>= 1) s += __shfl_xor_sync(0xffffffffu, s, o);
    float mu = s * (1.0f / DMOD);

    float d0 = v0.x - mu, d1 = v0.y - mu, d2 = v0.z - mu, d3 = v0.w - mu;
    float d4 = v1.x - mu, d5 = v1.y - mu, d6 = v1.z - mu, d7 = v1.w - mu;
    float q = d0*d0 + d1*d1 + d2*d2 + d3*d3 + d4*d4 + d5*d5 + d6*d6 + d7*d7;
    #pragma unroll
    for (int o = 16; o > 0; o >>= 1) q += __shfl_xor_sync(0xffffffffu, q, o);
    float rstd = rsqrtf(q * (1.0f / DMOD) + 1e-5f);

    const float4* gp = (const float4*)g;
    const float4* bp = (const float4*)b;
    float4 g0 = gp[lane * 2], g1 = gp[lane * 2 + 1];
    float4 b0 = bp[lane * 2], b1 = bp[lane * 2 + 1];

    float o0 = d0 * rstd * g0.x + b0.x, o1 = d1 * rstd * g0.y + b0.y;
    float o2 = d2 * rstd * g0.z + b0.z, o3 = d3 * rstd * g0.w + b0.w;
    float o4 = d4 * rstd * g1.x + b1.x, o5 = d5 * rstd * g1.y + b1.y;
    float o6 = d6 * rstd * g1.z + b1.z, o7 = d7 * rstd * g1.w + b1.w;

    uint32_t h, l;
    int base = tok * 128 + lane * 4;
    split2(o0, o1, h, l);  yh[base + 0] = h;  yl[base + 0] = l;
    split2(o2, o3, h, l);  yh[base + 1] = h;  yl[base + 1] = l;
    split2(o4, o5, h, l);  yh[base + 2] = h;  yl[base + 2] = l;
    split2(o6, o7, h, l);  yh[base + 3] = h;  yl[base + 3] = l;
}

// ---------------- masked flash attention (fp32, float4), bf16 hi/lo out ----------------
__global__ __launch_bounds__(256) void attn_kernel(
    const float* __restrict__ qkv,
    uint32_t* __restrict__ oh, uint32_t* __restrict__ ol)
{
    int mh   = blockIdx.x;
    int m    = mh >> 3;
    int h    = mh & 7;
    int qrow = blockIdx.y * 256 + threadIdx.x;

    __shared__ float4 Ksh[128][8];
    __shared__ float4 Vsh[128][8];

    const float* base = qkv + (size_t)(m * NTOK) * (3 * DMOD);
    const float scale = 0.17677669529663687f;

    float4 q[8];
    {
        const float4* qp = (const float4*)(base + (size_t)qrow * (3 * DMOD) + h * DHD);
        #pragma unroll
        for (int i = 0; i < 8; i++) q[i] = qp[i];
    }

    float mval = -INFINITY, ssum = 0.0f;
    float4 o[8];
    #pragma unroll
    for (int i = 0; i < 8; i++) o[i] = make_float4(0.f, 0.f, 0.f, 0.f);

    for (int c = 0; c < 4; c++) {
        __syncthreads();
        for (int i = threadIdx.x; i < 128 * 8; i += 256) {
            int kr = c * 128 + (i >> 3);
            int dd = i & 7;
            const float4* kp = (const float4*)(base + (size_t)kr * (3 * DMOD) + DMOD + h * DHD);
            const float4* vp = (const float4*)(base + (size_t)kr * (3 * DMOD) + 2 * DMOD + h * DHD);
            Ksh[i >> 3][dd] = kp[dd];
            Vsh[i >> 3][dd] = vp[dd];
        }
        __syncthreads();

        for (int j = 0; j < 128; j++) {
            float s = 0.0f;
            #pragma unroll
            for (int i = 0; i < 8; i++) {
                float4 kk = Ksh[j][i];
                s += q[i].x * kk.x + q[i].y * kk.y + q[i].z * kk.z + q[i].w * kk.w;
            }
            s *= scale;
            if (s > mval) {
                float corr = __expf(mval - s);
                ssum *= corr;
                #pragma unroll
                for (int i = 0; i < 8; i++) {
                    o[i].x *= corr; o[i].y *= corr; o[i].z *= corr; o[i].w *= corr;
                }
                mval = s;
            }
            float p = __expf(s - mval);
            ssum += p;
            #pragma unroll
            for (int i = 0; i < 8; i++) {
                float4 vv = Vsh[j][i];
                o[i].x += p * vv.x; o[i].y += p * vv.y;
                o[i].z += p * vv.z; o[i].w += p * vv.w;
            }
        }
    }

    if (qrow >= NCC) {
        const float4* kp = (const float4*)(base + (size_t)qrow * (3 * DMOD) + DMOD + h * DHD);
        const float4* vp = (const float4*)(base + (size_t)qrow * (3 * DMOD) + 2 * DMOD + h * DHD);
        float s = 0.0f;
        #pragma unroll
        for (int i = 0; i < 8; i++) {
            float4 kk = kp[i];
            s += q[i].x * kk.x + q[i].y * kk.y + q[i].z * kk.z + q[i].w * kk.w;
        }
        s *= scale;
        if (s > mval) {
            float corr = __expf(mval - s);
            ssum *= corr;
            #pragma unroll
            for (int i = 0; i < 8; i++) {
                o[i].x *= corr; o[i].y *= corr; o[i].z *= corr; o[i].w *= corr;
            }
            mval = s;
        }
        float p = __expf(s - mval);
        ssum += p;
        #pragma unroll
        for (int i = 0; i < 8; i++) {
            float4 vv = vp[i];
            o[i].x += p * vv.x; o[i].y += p * vv.y;
            o[i].z += p * vv.z; o[i].w += p * vv.w;
        }
    }

    float inv = 1.0f / ssum;
    int base32 = ((m * NTOK + qrow) * DMOD + h * DHD) >> 1;
    #pragma unroll
    for (int i = 0; i < 8; i++) {
        uint32_t hh, ll;
        split2(o[i].x * inv, o[i].y * inv, hh, ll);
        oh[base32 + i * 2]     = hh;
        ol[base32 + i * 2]     = ll;
        split2(o[i].z * inv, o[i].w * inv, hh, ll);
        oh[base32 + i * 2 + 1] = hh;
        ol[base32 + i * 2 + 1] = ll;
    }
}

// ---------------- launch ----------------
#define BF16P(sym) ((const __nv_bfloat16*)sym)

extern "C" void kernel_launch(void* const* d_in, const int* in_sizes, int n_in,
                              void* d_out, int out_size)
{
    const float* xc     = (const float*)d_in[0];
    const float* yc     = (const float*)d_in[1];
    const float* xt     = (const float*)d_in[2];
    const float* enc_W1 = (const float*)d_in[3];
    const float* enc_b1 = (const float*)d_in[4];
    const float* enc_W2 = (const float*)d_in[5];
    const float* enc_b2 = (const float*)d_in[6];
    const float* Wqkv   = (const float*)d_in[7];
    const float* bqkv   = (const float*)d_in[8];
    const float* Wo     = (const float*)d_in[9];
    const float* bo     = (const float*)d_in[10];
    const float* ln1_g  = (const float*)d_in[11];
    const float* ln1_b  = (const float*)d_in[12];
    const float* ln2_g  = (const float*)d_in[13];
    const float* ln2_b  = (const float*)d_in[14];
    const float* Wff1   = (const float*)d_in[15];
    const float* bff1   = (const float*)d_in[16];
    const float* Wff2   = (const float*)d_in[17];
    const float* bff2   = (const float*)d_in[18];
    float* out          = (float*)d_out;

    float *z, *qkv;
    uint32_t *hh, *hl, *ah, *al, *fh, *fl;
    uint32_t *wqh, *wql, *woh, *wol, *w1h, *w1l, *w2h, *w2l, *ewh, *ewl;
    cudaGetSymbolAddress((void**)&z,   g_z);
    cudaGetSymbolAddress((void**)&qkv, g_qkv);
    cudaGetSymbolAddress((void**)&hh,  g_h_h);   cudaGetSymbolAddress((void**)&hl,  g_h_l);
    cudaGetSymbolAddress((void**)&ah,  g_att_h); cudaGetSymbolAddress((void**)&al,  g_att_l);
    cudaGetSymbolAddress((void**)&fh,  g_ff_h);  cudaGetSymbolAddress((void**)&fl,  g_ff_l);
    cudaGetSymbolAddress((void**)&wqh, g_wqkv_h); cudaGetSymbolAddress((void**)&wql, g_wqkv_l);
    cudaGetSymbolAddress((void**)&woh, g_wo_h);   cudaGetSymbolAddress((void**)&wol, g_wo_l);
    cudaGetSymbolAddress((void**)&w1h, g_wff1_h); cudaGetSymbolAddress((void**)&w1l, g_wff1_l);
    cudaGetSymbolAddress((void**)&w2h, g_wff2_h); cudaGetSymbolAddress((void**)&w2l, g_wff2_l);
    cudaGetSymbolAddress((void**)&ewh, g_ew2_h);  cudaGetSymbolAddress((void**)&ewl, g_ew2_l);

    cudaFuncSetAttribute(gemm_bf3<0>, cudaFuncAttributeMaxDynamicSharedMemorySize, GEMM_SMEM);
    cudaFuncSetAttribute(gemm_bf3<1>, cudaFuncAttributeMaxDynamicSharedMemorySize, GEMM_SMEM);
    cudaFuncSetAttribute(gemm_bf3<2>, cudaFuncAttributeMaxDynamicSharedMemorySize, GEMM_SMEM);

    // ---- weight splits ----
    auto splitw = [&](const float* src, uint32_t* hi, uint32_t* lo, int npairs) {
        split_kernel<<<(npairs + 255) / 256, 256>>>(src, hi, lo, npairs);
    };
    splitw(enc_W2, ewh, ewl, DMOD * DMOD / 2);
    splitw(Wqkv,   wqh, wql, NLAY * DMOD * 3 * DMOD / 2);
    splitw(Wo,     woh, wol, NLAY * DMOD * DMOD / 2);
    splitw(Wff1,   w1h, w1l, NLAY * DMOD * FFD / 2);
    splitw(Wff2,   w2h, w2l, NLAY * FFD * DMOD / 2);

    // ---- encoder ----
    encode_hidden<<<TOK, 128>>>(xc, yc, xt, enc_W1, enc_b1, hh, hl);
    gemm_bf3<0><<<dim3(DMOD / BN, TOK / BM), 128, GEMM_SMEM>>>(
        BF16P(hh), BF16P(hl), BF16P(ewh), BF16P(ewl),
        enc_b2, nullptr, z, nullptr, nullptr, DMOD, DMOD);

    for (int l = 0; l < NLAY; l++) {
        const uint32_t* wq_h = wqh + (size_t)l * DMOD * 3 * DMOD / 2;
        const uint32_t* wq_l = wql + (size_t)l * DMOD * 3 * DMOD / 2;
        const uint32_t* wo_h = woh + (size_t)l * DMOD * DMOD / 2;
        const uint32_t* wo_l = wol + (size_t)l * DMOD * DMOD / 2;
        const uint32_t* f1_h = w1h + (size_t)l * DMOD * FFD / 2;
        const uint32_t* f1_l = w1l + (size_t)l * DMOD * FFD / 2;
        const uint32_t* f2_h = w2h + (size_t)l * FFD * DMOD / 2;
        const uint32_t* f2_l = w2l + (size_t)l * FFD * DMOD / 2;

        ln_kernel<<<TOK / 8, 256>>>(z, ln1_g + l * DMOD, ln1_b + l * DMOD, hh, hl);
        gemm_bf3<0><<<dim3(3 * DMOD / BN, TOK / BM), 128, GEMM_SMEM>>>(
            BF16P(hh), BF16P(hl), BF16P(wq_h), BF16P(wq_l),
            bqkv + l * 3 * DMOD, nullptr, qkv, nullptr, nullptr, DMOD, 3 * DMOD);
        attn_kernel<<<dim3(MB * NH, NTOK / 256), 256>>>(qkv, ah, al);
        gemm_bf3<1><<<dim3(DMOD / BN, TOK / BM), 128, GEMM_SMEM>>>(
            BF16P(ah), BF16P(al), BF16P(wo_h), BF16P(wo_l),
            bo + l * DMOD, z, z, nullptr, nullptr, DMOD, DMOD);
        ln_kernel<<<TOK / 8, 256>>>(z, ln2_g + l * DMOD, ln2_b + l * DMOD, hh, hl);
        gemm_bf3<2><<<dim3(FFD / BN, TOK / BM), 128, GEMM_SMEM>>>(
            BF16P(hh), BF16P(hl), BF16P(f1_h), BF16P(f1_l),
            bff1 + l * FFD, nullptr, nullptr, fh, fl, DMOD, FFD);
        float* dst = (l == NLAY - 1) ? out : z;
        gemm_bf3<1><<<dim3(DMOD / BN, TOK / BM), 128, GEMM_SMEM>>>(
            BF16P(fh), BF16P(fl), BF16P(f2_h), BF16P(f2_l),
            bff2 + l * DMOD, z, dst, nullptr, nullptr, FFD, DMOD);
    }
}

// round 7
// speedup vs baseline: 3.0397x; 1.6365x over previous
#include <cuda_runtime.h>
#include <cuda_bf16.h>
#include <math.h>
#include <stdint.h>

// ---------------- problem constants ----------------
#define MB    8
#define NCC   512
#define NTOK  1024
#define DMOD  256
#define NH    8
#define NLAY  6
#define FFD   1024
#define DHD   32
#define TOK   (MB * NTOK)   // 8192

// ---------------- device scratch ----------------
__device__ float g_z[TOK * DMOD];
// split activations (bf16 hi/lo packed as uint32 pairs)
__device__ uint32_t g_h_h[TOK * DMOD / 2],  g_h_l[TOK * DMOD / 2];
__device__ uint32_t g_qkv_h[TOK * 3 * DMOD / 2], g_qkv_l[TOK * 3 * DMOD / 2];
__device__ uint32_t g_att_h[TOK * DMOD / 2], g_att_l[TOK * DMOD / 2];
__device__ uint32_t g_ff_h[TOK * FFD / 2],   g_ff_l[TOK * FFD / 2];
// split weights
__device__ uint32_t g_wqkv_h[NLAY * DMOD * 3 * DMOD / 2], g_wqkv_l[NLAY * DMOD * 3 * DMOD / 2];
__device__ uint32_t g_wo_h[NLAY * DMOD * DMOD / 2],       g_wo_l[NLAY * DMOD * DMOD / 2];
__device__ uint32_t g_wff1_h[NLAY * DMOD * FFD / 2],      g_wff1_l[NLAY * DMOD * FFD / 2];
__device__ uint32_t g_wff2_h[NLAY * FFD * DMOD / 2],      g_wff2_l[NLAY * FFD * DMOD / 2];
__device__ uint32_t g_ew2_h[DMOD * DMOD / 2],             g_ew2_l[DMOD * DMOD / 2];

// ---------------- helpers ----------------
__device__ __forceinline__ void split2(float x0, float x1, uint32_t& h, uint32_t& l) {
    uint32_t hh;
    asm("cvt.rn.bf16x2.f32 %0, %1, %2;" : "=r"(hh) : "f"(x1), "f"(x0));
    float h0f = __uint_as_float(hh << 16);
    float h1f = __uint_as_float(hh & 0xffff0000u);
    h = hh;
    float l0 = x0 - h0f, l1 = x1 - h1f;
    asm("cvt.rn.bf16x2.f32 %0, %1, %2;" : "=r"(l) : "f"(l1), "f"(l0));
}
__device__ __forceinline__ float bflo(uint32_t v) { return __uint_as_float(v << 16); }
__device__ __forceinline__ float bfhi(uint32_t v) { return __uint_as_float(v & 0xffff0000u); }

__device__ __forceinline__ void cp_async16(void* dst, const void* src) {
    uint32_t d = (uint32_t)__cvta_generic_to_shared(dst);
    asm volatile("cp.async.cg.shared.global [%0], [%1], 16;\n" :: "r"(d), "l"(src));
}
__device__ __forceinline__ void cp_commit() { asm volatile("cp.async.commit_group;\n"); }
template <int N>
__device__ __forceinline__ void cp_wait() { asm volatile("cp.async.wait_group %0;\n" :: "n"(N)); }

#define LDM4(R0, R1, R2, R3, ADDR)                                          \
    asm volatile("ldmatrix.sync.aligned.m8n8.x4.shared.b16 {%0,%1,%2,%3}, [%4];" \
                 : "=r"(R0), "=r"(R1), "=r"(R2), "=r"(R3) : "r"(ADDR))

#define LDM4T(R0, R1, R2, R3, ADDR)                                         \
    asm volatile("ldmatrix.sync.aligned.m8n8.x4.trans.shared.b16 {%0,%1,%2,%3}, [%4];" \
                 : "=r"(R0), "=r"(R1), "=r"(R2), "=r"(R3) : "r"(ADDR))

#define MMA_BF16(ACC, A0, A1, A2, A3, B0, B1)                               \
    asm volatile(                                                           \
        "mma.sync.aligned.m16n8k16.row.col.f32.bf16.bf16.f32 "             \
        "{%0,%1,%2,%3}, {%4,%5,%6,%7}, {%8,%9}, {%0,%1,%2,%3};"            \
        : "+f"((ACC)[0]), "+f"((ACC)[1]), "+f"((ACC)[2]), "+f"((ACC)[3])   \
        : "r"(A0), "r"(A1), "r"(A2), "r"(A3), "r"(B0), "r"(B1))

// ---------------- weight split: fp32 -> bf16 hi/lo ----------------
__global__ void split_kernel(const float* __restrict__ src,
                             uint32_t* __restrict__ hi, uint32_t* __restrict__ lo,
                             int npairs)
{
    int i = blockIdx.x * 256 + threadIdx.x;
    if (i < npairs) {
        uint32_t h, l;
        split2(src[2 * i], src[2 * i + 1], h, l);
        hi[i] = h;
        lo[i] = l;
    }
}

// ---------------- pure-bf16 3-pass tensor-core GEMM (256 thr, 8 warps) ----------------
#define BM 128
#define BN 128
#define BK 32
#define AST 40    // bf16 stride (80 B rows)
#define BST 136   // bf16 stride (272 B rows)
#define ASTB 80
#define BSTB 272
#define GEMM_SMEM ((2*BM*AST + 2*BK*BST) * 2 * 2)   // 75776 bytes

// OUTMODE: 0 fp32, 1 fp32+resid, 2 relu+split, 3 split
template <int OUTMODE>
__global__ __launch_bounds__(256) void gemm_bf3(
    const __nv_bfloat16* __restrict__ Ah, const __nv_bfloat16* __restrict__ Al,
    const __nv_bfloat16* __restrict__ Bh, const __nv_bfloat16* __restrict__ Bl,
    const float* __restrict__ bias, const float* __restrict__ Rsd,
    float* __restrict__ C, uint32_t* __restrict__ Chi, uint32_t* __restrict__ Clo,
    int K, int N)
{
    extern __shared__ char smem_raw[];
    __nv_bfloat16* sAh = (__nv_bfloat16*)smem_raw;
    __nv_bfloat16* sAl = sAh + 2 * BM * AST;
    __nv_bfloat16* sBh = sAl + 2 * BM * AST;
    __nv_bfloat16* sBl = sBh + 2 * BK * BST;

    const int tid = threadIdx.x;
    const int warp = tid >> 5, lane = tid & 31;
    const int g = lane >> 2, tg = lane & 3;
    const int wy = warp >> 2, wx = warp & 3;   // 2x4 warps; warp tile 64x32
    const int row0 = blockIdx.y * BM, col0 = blockIdx.x * BN;

    float acc[4][4][4];
    #pragma unroll
    for (int a = 0; a < 4; a++)
        #pragma unroll
        for (int b = 0; b < 4; b++)
            #pragma unroll
            for (int c = 0; c < 4; c++) acc[a][b][c] = 0.0f;

    auto issue = [&](int t, int b) {
        #pragma unroll
        for (int j = 0; j < 2; j++) {
            int i = tid * 2 + j;
            int arow = i >> 2, aseg = i & 3;
            cp_async16(sAh + b * BM * AST + arow * AST + aseg * 8,
                       Ah + (size_t)(row0 + arow) * K + t * BK + aseg * 8);
            cp_async16(sAl + b * BM * AST + arow * AST + aseg * 8,
                       Al + (size_t)(row0 + arow) * K + t * BK + aseg * 8);
            int brow = i >> 4, bseg = i & 15;
            cp_async16(sBh + b * BK * BST + brow * BST + bseg * 8,
                       Bh + (size_t)(t * BK + brow) * N + col0 + bseg * 8);
            cp_async16(sBl + b * BK * BST + brow * BST + bseg * 8,
                       Bl + (size_t)(t * BK + brow) * N + col0 + bseg * 8);
        }
        cp_commit();
    };

    const int a_lane = (wy * 64 + (lane & 15)) * ASTB + (lane >> 4) * 16;
    const int b_lane = (lane & 15) * BSTB + (lane >> 4) * 16 + wx * 64;

    auto compute = [&](int b) {
        uint32_t aHb = (uint32_t)__cvta_generic_to_shared(sAh + b * BM * AST) + a_lane;
        uint32_t aLb = (uint32_t)__cvta_generic_to_shared(sAl + b * BM * AST) + a_lane;
        uint32_t bHb = (uint32_t)__cvta_generic_to_shared(sBh + b * BK * BST) + b_lane;
        uint32_t bLb = (uint32_t)__cvta_generic_to_shared(sBl + b * BK * BST) + b_lane;

        #pragma unroll
        for (int ks = 0; ks < 2; ks++) {
            uint32_t ah[4][4], al[4][4], bh[2][4], bl[2][4];
            #pragma unroll
            for (int mi = 0; mi < 4; mi++) {
                LDM4(ah[mi][0], ah[mi][1], ah[mi][2], ah[mi][3],
                     aHb + mi * 16 * ASTB + ks * 32);
                LDM4(al[mi][0], al[mi][1], al[mi][2], al[mi][3],
                     aLb + mi * 16 * ASTB + ks * 32);
            }
            #pragma unroll
            for (int nc = 0; nc < 2; nc++) {
                LDM4T(bh[nc][0], bh[nc][1], bh[nc][2], bh[nc][3],
                      bHb + ks * 16 * BSTB + nc * 32);
                LDM4T(bl[nc][0], bl[nc][1], bl[nc][2], bl[nc][3],
                      bLb + ks * 16 * BSTB + nc * 32);
            }
            #pragma unroll
            for (int mi = 0; mi < 4; mi++)
                #pragma unroll
                for (int nf = 0; nf < 4; nf++) {
                    const int p = nf >> 1, q = (nf & 1) * 2;
                    MMA_BF16(acc[mi][nf], al[mi][0], al[mi][1], al[mi][2], al[mi][3],
                             bh[p][q], bh[p][q + 1]);
                    MMA_BF16(acc[mi][nf], ah[mi][0], ah[mi][1], ah[mi][2], ah[mi][3],
                             bl[p][q], bl[p][q + 1]);
                    MMA_BF16(acc[mi][nf], ah[mi][0], ah[mi][1], ah[mi][2], ah[mi][3],
                             bh[p][q], bh[p][q + 1]);
                }
        }
    };

    const int T = K / BK;
    issue(0, 0);
    for (int t = 0; t < T; t++) {
        const int buf = t & 1;
        if (t + 1 < T) {
            issue(t + 1, buf ^ 1);
            cp_wait<1>();
        } else {
            cp_wait<0>();
        }
        __syncthreads();
        compute(buf);
        __syncthreads();
    }

    #pragma unroll
    for (int mi = 0; mi < 4; mi++) {
        #pragma unroll
        for (int nf = 0; nf < 4; nf++) {
            const int r = row0 + wy * 64 + mi * 16 + g;
            const int c = col0 + wx * 32 + nf * 8 + tg * 2;
            const float b0 = bias[c], b1 = bias[c + 1];
            float v0 = acc[mi][nf][0] + b0;
            float v1 = acc[mi][nf][1] + b1;
            float v2 = acc[mi][nf][2] + b0;
            float v3 = acc[mi][nf][3] + b1;
            if (OUTMODE >= 2) {
                if (OUTMODE == 2) {
                    v0 = fmaxf(v0, 0.0f); v1 = fmaxf(v1, 0.0f);
                    v2 = fmaxf(v2, 0.0f); v3 = fmaxf(v3, 0.0f);
                }
                uint32_t h, l;
                split2(v0, v1, h, l);
                Chi[((size_t)r * N + c) >> 1] = h;
                Clo[((size_t)r * N + c) >> 1] = l;
                split2(v2, v3, h, l);
                Chi[((size_t)(r + 8) * N + c) >> 1] = h;
                Clo[((size_t)(r + 8) * N + c) >> 1] = l;
            } else {
                if (OUTMODE == 1) {
                    v0 += Rsd[(size_t)r * N + c];
                    v1 += Rsd[(size_t)r * N + c + 1];
                    v2 += Rsd[(size_t)(r + 8) * N + c];
                    v3 += Rsd[(size_t)(r + 8) * N + c + 1];
                }
                *(float2*)&C[(size_t)r * N + c]       = make_float2(v0, v1);
                *(float2*)&C[(size_t)(r + 8) * N + c] = make_float2(v2, v3);
            }
        }
    }
}

// ---------------- tensor-core flash attention ----------------
// Block: 128 thr (4 warps), 64 q rows for one (m,h). K/V chunks of 64 keys.
// qkv stored as split bf16 hi/lo ([tok][768] pairs). 3-pass QK and PV.
#define QST 40
#define QSTB 80
#define ATTN_SMEM ((2*64*QST + 8*64*QST) * 2)   // 51200 bytes

__global__ __launch_bounds__(128) void attn_mma(
    const uint32_t* __restrict__ qh, const uint32_t* __restrict__ ql,
    uint32_t* __restrict__ oh, uint32_t* __restrict__ ol)
{
    extern __shared__ char sm[];
    __nv_bfloat16* sQh = (__nv_bfloat16*)sm;
    __nv_bfloat16* sQl = sQh + 64 * QST;
    __nv_bfloat16* sKh = sQl + 64 * QST;     // [2][64*QST]
    __nv_bfloat16* sKl = sKh + 2 * 64 * QST;
    __nv_bfloat16* sVh = sKl + 2 * 64 * QST;
    __nv_bfloat16* sVl = sVh + 2 * 64 * QST;

    const int mh = blockIdx.x, qb = blockIdx.y;
    const int m = mh >> 3, h = mh & 7;
    const int q0 = qb * 64;
    const int tid = threadIdx.x, warp = tid >> 5, lane = tid & 31;
    const int g = lane >> 2, tg = lane & 3;
    const int tb = m * NTOK;
    const float scale = 0.17677669529663687f;   // 1/sqrt(32)

    const int i0 = tid * 2;
    const int lrow0 = i0 >> 2, lseg0 = i0 & 3;
    const int lrow1 = (i0 + 1) >> 2, lseg1 = (i0 + 1) & 3;

    // ---- Q load ----
    {
        size_t s0 = (size_t)(tb + q0 + lrow0) * 384 + h * 16 + lseg0 * 4;
        size_t s1 = (size_t)(tb + q0 + lrow1) * 384 + h * 16 + lseg1 * 4;
        cp_async16(sQh + lrow0 * QST + lseg0 * 8, qh + s0);
        cp_async16(sQh + lrow1 * QST + lseg1 * 8, qh + s1);
        cp_async16(sQl + lrow0 * QST + lseg0 * 8, ql + s0);
        cp_async16(sQl + lrow1 * QST + lseg1 * 8, ql + s1);
        cp_commit();
    }
    auto issueKV = [&](int c, int b) {
        int k0 = c * 64;
        size_t s0 = (size_t)(tb + k0 + lrow0) * 384 + 128 + h * 16 + lseg0 * 4;
        size_t s1 = (size_t)(tb + k0 + lrow1) * 384 + 128 + h * 16 + lseg1 * 4;
        __nv_bfloat16* kh = sKh + b * 64 * QST;
        __nv_bfloat16* kl = sKl + b * 64 * QST;
        __nv_bfloat16* vh = sVh + b * 64 * QST;
        __nv_bfloat16* vl = sVl + b * 64 * QST;
        cp_async16(kh + lrow0 * QST + lseg0 * 8, qh + s0);
        cp_async16(kh + lrow1 * QST + lseg1 * 8, qh + s1);
        cp_async16(kl + lrow0 * QST + lseg0 * 8, ql + s0);
        cp_async16(kl + lrow1 * QST + lseg1 * 8, ql + s1);
        cp_async16(vh + lrow0 * QST + lseg0 * 8, qh + s0 + 128);
        cp_async16(vh + lrow1 * QST + lseg1 * 8, qh + s1 + 128);
        cp_async16(vl + lrow0 * QST + lseg0 * 8, ql + s0 + 128);
        cp_async16(vl + lrow1 * QST + lseg1 * 8, ql + s1 + 128);
        cp_commit();
    };

    issueKV(0, 0);
    cp_wait<1>();
    __syncthreads();

    // ---- Q fragments (m16k16 x2 k-steps) ----
    uint32_t qfh[2][4], qfl[2][4];
    {
        uint32_t bh_ = (uint32_t)__cvta_generic_to_shared(sQh) +
                       (warp * 16 + (lane & 15)) * QSTB + (lane >> 4) * 16;
        uint32_t bl_ = (uint32_t)__cvta_generic_to_shared(sQl) +
                       (warp * 16 + (lane & 15)) * QSTB + (lane >> 4) * 16;
        LDM4(qfh[0][0], qfh[0][1], qfh[0][2], qfh[0][3], bh_);
        LDM4(qfh[1][0], qfh[1][1], qfh[1][2], qfh[1][3], bh_ + 32);
        LDM4(qfl[0][0], qfl[0][1], qfl[0][2], qfl[0][3], bl_);
        LDM4(qfl[1][0], qfl[1][1], qfl[1][2], qfl[1][3], bl_ + 32);
    }

    float mx0 = -1e30f, mx1 = -1e30f, sum0 = 0.f, sum1 = 0.f;
    float oacc[4][4];
    #pragma unroll
    for (int a = 0; a < 4; a++)
        #pragma unroll
        for (int b = 0; b < 4; b++) oacc[a][b] = 0.f;

    const uint32_t kbyte = ((lane & 7) + ((lane >> 4) & 1) * 8) * QSTB +
                           ((lane >> 3) & 1) * 16;
    const uint32_t vbyte = (lane & 15) * QSTB + (lane >> 4) * 16;

    for (int c = 0; c < 8; c++) {
        const int b = c & 1;
        if (c + 1 < 8) { issueKV(c + 1, b ^ 1); cp_wait<1>(); }
        else           { cp_wait<0>(); }
        __syncthreads();

        uint32_t khb = (uint32_t)__cvta_generic_to_shared(sKh + b * 64 * QST) + kbyte;
        uint32_t klb = (uint32_t)__cvta_generic_to_shared(sKl + b * 64 * QST) + kbyte;

        // ---- S = Q K^T (3-pass) ----
        float sacc[8][4];
        #pragma unroll
        for (int a = 0; a < 8; a++)
            #pragma unroll
            for (int j = 0; j < 4; j++) sacc[a][j] = 0.f;

        #pragma unroll
        for (int nk = 0; nk < 4; nk++) {
            uint32_t kh0[4], kh1[4], kl0[4], kl1[4];
            LDM4(kh0[0], kh0[1], kh0[2], kh0[3], khb + nk * 16 * QSTB);
            LDM4(kh1[0], kh1[1], kh1[2], kh1[3], khb + nk * 16 * QSTB + 32);
            LDM4(kl0[0], kl0[1], kl0[2], kl0[3], klb + nk * 16 * QSTB);
            LDM4(kl1[0], kl1[1], kl1[2], kl1[3], klb + nk * 16 * QSTB + 32);
            // nfrag A = keys nk*16+0..7: regs [0],[1]; nfrag B = +8..15: [2],[3]
            MMA_BF16(sacc[nk*2], qfl[0][0], qfl[0][1], qfl[0][2], qfl[0][3], kh0[0], kh0[1]);
            MMA_BF16(sacc[nk*2], qfl[1][0], qfl[1][1], qfl[1][2], qfl[1][3], kh1[0], kh1[1]);
            MMA_BF16(sacc[nk*2], qfh[0][0], qfh[0][1], qfh[0][2], qfh[0][3], kl0[0], kl0[1]);
            MMA_BF16(sacc[nk*2], qfh[1][0], qfh[1][1], qfh[1][2], qfh[1][3], kl1[0], kl1[1]);
            MMA_BF16(sacc[nk*2], qfh[0][0], qfh[0][1], qfh[0][2], qfh[0][3], kh0[0], kh0[1]);
            MMA_BF16(sacc[nk*2], qfh[1][0], qfh[1][1], qfh[1][2], qfh[1][3], kh1[0], kh1[1]);
            MMA_BF16(sacc[nk*2+1], qfl[0][0], qfl[0][1], qfl[0][2], qfl[0][3], kh0[2], kh0[3]);
            MMA_BF16(sacc[nk*2+1], qfl[1][0], qfl[1][1], qfl[1][2], qfl[1][3], kh1[2], kh1[3]);
            MMA_BF16(sacc[nk*2+1], qfh[0][0], qfh[0][1], qfh[0][2], qfh[0][3], kl0[2], kl0[3]);
            MMA_BF16(sacc[nk*2+1], qfh[1][0], qfh[1][1], qfh[1][2], qfh[1][3], kl1[2], kl1[3]);
            MMA_BF16(sacc[nk*2+1], qfh[0][0], qfh[0][1], qfh[0][2], qfh[0][3], kh0[2], kh0[3]);
            MMA_BF16(sacc[nk*2+1], qfh[1][0], qfh[1][1], qfh[1][2], qfh[1][3], kh1[2], kh1[3]);
        }

        // ---- online softmax ----
        float cm0 = -1e30f, cm1 = -1e30f;
        #pragma unroll
        for (int a = 0; a < 8; a++) {
            #pragma unroll
            for (int j = 0; j < 4; j++) sacc[a][j] *= scale;
            cm0 = fmaxf(cm0, fmaxf(sacc[a][0], sacc[a][1]));
            cm1 = fmaxf(cm1, fmaxf(sacc[a][2], sacc[a][3]));
        }
        cm0 = fmaxf(cm0, __shfl_xor_sync(~0u, cm0, 1));
        cm0 = fmaxf(cm0, __shfl_xor_sync(~0u, cm0, 2));
        cm1 = fmaxf(cm1, __shfl_xor_sync(~0u, cm1, 1));
        cm1 = fmaxf(cm1, __shfl_xor_sync(~0u, cm1, 2));
        float nm0 = fmaxf(mx0, cm0), nm1 = fmaxf(mx1, cm1);
        float c0 = __expf(mx0 - nm0), c1 = __expf(mx1 - nm1);
        sum0 *= c0; sum1 *= c1;
        #pragma unroll
        for (int a = 0; a < 4; a++) {
            oacc[a][0] *= c0; oacc[a][1] *= c0;
            oacc[a][2] *= c1; oacc[a][3] *= c1;
        }
        #pragma unroll
        for (int a = 0; a < 8; a++) {
            sacc[a][0] = __expf(sacc[a][0] - nm0);
            sacc[a][1] = __expf(sacc[a][1] - nm0);
            sacc[a][2] = __expf(sacc[a][2] - nm1);
            sacc[a][3] = __expf(sacc[a][3] - nm1);
            sum0 += sacc[a][0] + sacc[a][1];
            sum1 += sacc[a][2] + sacc[a][3];
        }
        mx0 = nm0; mx1 = nm1;

        // ---- pack P as A-fragments (hi/lo) ----
        uint32_t pah[4][4], pal[4][4];
        #pragma unroll
        for (int kf = 0; kf < 4; kf++) {
            split2(sacc[kf*2][0],   sacc[kf*2][1],   pah[kf][0], pal[kf][0]);
            split2(sacc[kf*2][2],   sacc[kf*2][3],   pah[kf][1], pal[kf][1]);
            split2(sacc[kf*2+1][0], sacc[kf*2+1][1], pah[kf][2], pal[kf][2]);
            split2(sacc[kf*2+1][2], sacc[kf*2+1][3], pah[kf][3], pal[kf][3]);
        }

        // ---- O += P V (3-pass) ----
        uint32_t vhb = (uint32_t)__cvta_generic_to_shared(sVh + b * 64 * QST) + vbyte;
        uint32_t vlb = (uint32_t)__cvta_generic_to_shared(sVl + b * 64 * QST) + vbyte;
        #pragma unroll
        for (int nc = 0; nc < 2; nc++) {
            #pragma unroll
            for (int kf = 0; kf < 4; kf++) {
                uint32_t vh_[4], vl_[4];
                LDM4T(vh_[0], vh_[1], vh_[2], vh_[3], vhb + kf * 16 * QSTB + nc * 32);
                LDM4T(vl_[0], vl_[1], vl_[2], vl_[3], vlb + kf * 16 * QSTB + nc * 32);
                MMA_BF16(oacc[nc*2], pal[kf][0], pal[kf][1], pal[kf][2], pal[kf][3], vh_[0], vh_[1]);
                MMA_BF16(oacc[nc*2], pah[kf][0], pah[kf][1], pah[kf][2], pah[kf][3], vl_[0], vl_[1]);
                MMA_BF16(oacc[nc*2], pah[kf][0], pah[kf][1], pah[kf][2], pah[kf][3], vh_[0], vh_[1]);
                MMA_BF16(oacc[nc*2+1], pal[kf][0], pal[kf][1], pal[kf][2], pal[kf][3], vh_[2], vh_[3]);
                MMA_BF16(oacc[nc*2+1], pah[kf][0], pah[kf][1], pah[kf][2], pah[kf][3], vl_[2], vl_[3]);
                MMA_BF16(oacc[nc*2+1], pah[kf][0], pah[kf][1], pah[kf][2], pah[kf][3], vh_[2], vh_[3]);
            }
        }
        __syncthreads();
    }

    // ---- self key for target rows ----
    if (q0 >= NCC) {
        #pragma unroll
        for (int half = 0; half < 2; half++) {
            int row = q0 + warp * 16 + g + half * 8;
            size_t pb = (size_t)(tb + row) * 384;
            float dot = 0.f;
            #pragma unroll
            for (int w = 0; w < 4; w++) {
                uint32_t qhv = qh[pb + h * 16 + tg * 4 + w];
                uint32_t qlv = ql[pb + h * 16 + tg * 4 + w];
                uint32_t khv = qh[pb + 128 + h * 16 + tg * 4 + w];
                uint32_t klv = ql[pb + 128 + h * 16 + tg * 4 + w];
                float qa = bflo(qhv) + bflo(qlv), qb_ = bfhi(qhv) + bfhi(qlv);
                float ka = bflo(khv) + bflo(klv), kb = bfhi(khv) + bfhi(klv);
                dot += qa * ka + qb_ * kb;
            }
            dot += __shfl_xor_sync(~0u, dot, 1);
            dot += __shfl_xor_sync(~0u, dot, 2);
            float s = dot * scale;
            float mxv = half ? mx1 : mx0;
            float nm = fmaxf(mxv, s);
            float corr = __expf(mxv - nm);
            float p = __expf(s - nm);
            if (half) { sum1 = sum1 * corr + (tg == 0 ? p : 0.f); mx1 = nm; }
            else      { sum0 = sum0 * corr + (tg == 0 ? p : 0.f); mx0 = nm; }
            #pragma unroll
            for (int nf = 0; nf < 4; nf++) {
                uint32_t vhv = qh[pb + 256 + h * 16 + nf * 4 + tg];
                uint32_t vlv = ql[pb + 256 + h * 16 + nf * 4 + tg];
                float v0 = bflo(vhv) + bflo(vlv);
                float v1 = bfhi(vhv) + bfhi(vlv);
                oacc[nf][half*2]   = oacc[nf][half*2]   * corr + p * v0;
                oacc[nf][half*2+1] = oacc[nf][half*2+1] * corr + p * v1;
            }
        }
    }

    // ---- finalize ----
    sum0 += __shfl_xor_sync(~0u, sum0, 1);
    sum0 += __shfl_xor_sync(~0u, sum0, 2);
    sum1 += __shfl_xor_sync(~0u, sum1, 1);
    sum1 += __shfl_xor_sync(~0u, sum1, 2);
    float inv0 = 1.f / sum0, inv1 = 1.f / sum1;

    int row = q0 + warp * 16 + g;
    size_t ob0 = ((size_t)(tb + row) * 256 + h * 32) >> 1;
    size_t ob1 = ((size_t)(tb + row + 8) * 256 + h * 32) >> 1;
    #pragma unroll
    for (int nf = 0; nf < 4; nf++) {
        uint32_t hh_, ll_;
        split2(oacc[nf][0] * inv0, oacc[nf][1] * inv0, hh_, ll_);
        oh[ob0 + nf * 4 + tg] = hh_;
        ol[ob0 + nf * 4 + tg] = ll_;
        split2(oacc[nf][2] * inv1, oacc[nf][3] * inv1, hh_, ll_);
        oh[ob1 + nf * 4 + tg] = hh_;
        ol[ob1 + nf * 4 + tg] = ll_;
    }
}

// ---------------- encoder layer-1 ----------------
__global__ __launch_bounds__(128) void encode_hidden(
    const float* __restrict__ xc, const float* __restrict__ yc,
    const float* __restrict__ xt,
    const float* __restrict__ W1, const float* __restrict__ b1,
    uint32_t* __restrict__ hh, uint32_t* __restrict__ hl)
{
    int tok = blockIdx.x;
    int m = tok >> 10, t = tok & 1023;
    int tid = threadIdx.x;
    int d = tid * 2;

    __shared__ float s_in[16];
    if (tid < 10) {
        float v;
        if (tid < 8) {
            v = (t < NCC) ? xc[(m * NCC + t) * 8 + tid]
                          : xt[(m * NCC + (t - NCC)) * 8 + tid];
        } else if (tid == 8) {
            v = (t < NCC) ? yc[m * NCC + t] : 0.0f;
        } else {
            v = (t < NCC) ? 0.0f : 1.0f;
        }
        s_in[tid] = v;
    }
    __syncthreads();

    float a0 = b1[d], a1 = b1[d + 1];
    #pragma unroll
    for (int k = 0; k < 10; k++) {
        a0 += s_in[k] * W1[k * DMOD + d];
        a1 += s_in[k] * W1[k * DMOD + d + 1];
    }
    uint32_t h, l;
    split2(fmaxf(a0, 0.0f), fmaxf(a1, 0.0f), h, l);
    hh[tok * 128 + tid] = h;
    hl[tok * 128 + tid] = l;
}

// ---------------- layernorm (warp/token), split bf16 output ----------------
__global__ __launch_bounds__(256) void ln_kernel(
    const float* __restrict__ x, const float* __restrict__ g,
    const float* __restrict__ b,
    uint32_t* __restrict__ yh, uint32_t* __restrict__ yl)
{
    int tok  = (blockIdx.x * 256 + threadIdx.x) >> 5;
    int lane = threadIdx.x & 31;

    const float4* xp = (const float4*)(x + (size_t)tok * DMOD);
    float4 v0 = xp[lane * 2], v1 = xp[lane * 2 + 1];

    float s = v0.x + v0.y + v0.z + v0.w + v1.x + v1.y + v1.z + v1.w;
    #pragma unroll
    for (int o = 16; o > 0; o >>= 1) s += __shfl_xor_sync(0xffffffffu, s, o);
    float mu = s * (1.0f / DMOD);

    float d0 = v0.x - mu, d1 = v0.y - mu, d2 = v0.z - mu, d3 = v0.w - mu;
    float d4 = v1.x - mu, d5 = v1.y - mu, d6 = v1.z - mu, d7 = v1.w - mu;
    float q = d0*d0 + d1*d1 + d2*d2 + d3*d3 + d4*d4 + d5*d5 + d6*d6 + d7*d7;
    #pragma unroll
    for (int o = 16; o > 0; o >>= 1) q += __shfl_xor_sync(0xffffffffu, q, o);
    float rstd = rsqrtf(q * (1.0f / DMOD) + 1e-5f);

    const float4* gp = (const float4*)g;
    const float4* bp = (const float4*)b;
    float4 g0 = gp[lane * 2], g1 = gp[lane * 2 + 1];
    float4 b0 = bp[lane * 2], b1 = bp[lane * 2 + 1];

    float o0 = d0 * rstd * g0.x + b0.x, o1 = d1 * rstd * g0.y + b0.y;
    float o2 = d2 * rstd * g0.z + b0.z, o3 = d3 * rstd * g0.w + b0.w;
    float o4 = d4 * rstd * g1.x + b1.x, o5 = d5 * rstd * g1.y + b1.y;
    float o6 = d6 * rstd * g1.z + b1.z, o7 = d7 * rstd * g1.w + b1.w;

    uint32_t h, l;
    int base = tok * 128 + lane * 4;
    split2(o0, o1, h, l);  yh[base + 0] = h;  yl[base + 0] = l;
    split2(o2, o3, h, l);  yh[base + 1] = h;  yl[base + 1] = l;
    split2(o4, o5, h, l);  yh[base + 2] = h;  yl[base + 2] = l;
    split2(o6, o7, h, l);  yh[base + 3] = h;  yl[base + 3] = l;
}

// ---------------- launch ----------------
#define BF16P(sym) ((const __nv_bfloat16*)sym)

extern "C" void kernel_launch(void* const* d_in, const int* in_sizes, int n_in,
                              void* d_out, int out_size)
{
    const float* xc     = (const float*)d_in[0];
    const float* yc     = (const float*)d_in[1];
    const float* xt     = (const float*)d_in[2];
    const float* enc_W1 = (const float*)d_in[3];
    const float* enc_b1 = (const float*)d_in[4];
    const float* enc_W2 = (const float*)d_in[5];
    const float* enc_b2 = (const float*)d_in[6];
    const float* Wqkv   = (const float*)d_in[7];
    const float* bqkv   = (const float*)d_in[8];
    const float* Wo     = (const float*)d_in[9];
    const float* bo     = (const float*)d_in[10];
    const float* ln1_g  = (const float*)d_in[11];
    const float* ln1_b  = (const float*)d_in[12];
    const float* ln2_g  = (const float*)d_in[13];
    const float* ln2_b  = (const float*)d_in[14];
    const float* Wff1   = (const float*)d_in[15];
    const float* bff1   = (const float*)d_in[16];
    const float* Wff2   = (const float*)d_in[17];
    const float* bff2   = (const float*)d_in[18];
    float* out          = (float*)d_out;

    float *z;
    uint32_t *hh, *hl, *qkh, *qkl, *ah, *al, *fh, *fl;
    uint32_t *wqh, *wql, *woh, *wol, *w1h, *w1l, *w2h, *w2l, *ewh, *ewl;
    cudaGetSymbolAddress((void**)&z,   g_z);
    cudaGetSymbolAddress((void**)&hh,  g_h_h);   cudaGetSymbolAddress((void**)&hl,  g_h_l);
    cudaGetSymbolAddress((void**)&qkh, g_qkv_h); cudaGetSymbolAddress((void**)&qkl, g_qkv_l);
    cudaGetSymbolAddress((void**)&ah,  g_att_h); cudaGetSymbolAddress((void**)&al,  g_att_l);
    cudaGetSymbolAddress((void**)&fh,  g_ff_h);  cudaGetSymbolAddress((void**)&fl,  g_ff_l);
    cudaGetSymbolAddress((void**)&wqh, g_wqkv_h); cudaGetSymbolAddress((void**)&wql, g_wqkv_l);
    cudaGetSymbolAddress((void**)&woh, g_wo_h);   cudaGetSymbolAddress((void**)&wol, g_wo_l);
    cudaGetSymbolAddress((void**)&w1h, g_wff1_h); cudaGetSymbolAddress((void**)&w1l, g_wff1_l);
    cudaGetSymbolAddress((void**)&w2h, g_wff2_h); cudaGetSymbolAddress((void**)&w2l, g_wff2_l);
    cudaGetSymbolAddress((void**)&ewh, g_ew2_h);  cudaGetSymbolAddress((void**)&ewl, g_ew2_l);

    cudaFuncSetAttribute(gemm_bf3<0>, cudaFuncAttributeMaxDynamicSharedMemorySize, GEMM_SMEM);
    cudaFuncSetAttribute(gemm_bf3<1>, cudaFuncAttributeMaxDynamicSharedMemorySize, GEMM_SMEM);
    cudaFuncSetAttribute(gemm_bf3<2>, cudaFuncAttributeMaxDynamicSharedMemorySize, GEMM_SMEM);
    cudaFuncSetAttribute(gemm_bf3<3>, cudaFuncAttributeMaxDynamicSharedMemorySize, GEMM_SMEM);
    cudaFuncSetAttribute(attn_mma,   cudaFuncAttributeMaxDynamicSharedMemorySize, ATTN_SMEM);

    auto splitw = [&](const float* src, uint32_t* hi, uint32_t* lo, int npairs) {
        split_kernel<<<(npairs + 255) / 256, 256>>>(src, hi, lo, npairs);
    };
    splitw(enc_W2, ewh, ewl, DMOD * DMOD / 2);
    splitw(Wqkv,   wqh, wql, NLAY * DMOD * 3 * DMOD / 2);
    splitw(Wo,     woh, wol, NLAY * DMOD * DMOD / 2);
    splitw(Wff1,   w1h, w1l, NLAY * DMOD * FFD / 2);
    splitw(Wff2,   w2h, w2l, NLAY * FFD * DMOD / 2);

    encode_hidden<<<TOK, 128>>>(xc, yc, xt, enc_W1, enc_b1, hh, hl);
    gemm_bf3<0><<<dim3(DMOD / BN, TOK / BM), 256, GEMM_SMEM>>>(
        BF16P(hh), BF16P(hl), BF16P(ewh), BF16P(ewl),
        enc_b2, nullptr, z, nullptr, nullptr, DMOD, DMOD);

    for (int l = 0; l < NLAY; l++) {
        const uint32_t* wq_h = wqh + (size_t)l * DMOD * 3 * DMOD / 2;
        const uint32_t* wq_l = wql + (size_t)l * DMOD * 3 * DMOD / 2;
        const uint32_t* wo_h = woh + (size_t)l * DMOD * DMOD / 2;
        const uint32_t* wo_l = wol + (size_t)l * DMOD * DMOD / 2;
        const uint32_t* f1_h = w1h + (size_t)l * DMOD * FFD / 2;
        const uint32_t* f1_l = w1l + (size_t)l * DMOD * FFD / 2;
        const uint32_t* f2_h = w2h + (size_t)l * FFD * DMOD / 2;
        const uint32_t* f2_l = w2l + (size_t)l * FFD * DMOD / 2;

        ln_kernel<<<TOK / 8, 256>>>(z, ln1_g + l * DMOD, ln1_b + l * DMOD, hh, hl);
        gemm_bf3<3><<<dim3(3 * DMOD / BN, TOK / BM), 256, GEMM_SMEM>>>(
            BF16P(hh), BF16P(hl), BF16P(wq_h), BF16P(wq_l),
            bqkv + l * 3 * DMOD, nullptr, nullptr, qkh, qkl, DMOD, 3 * DMOD);
        attn_mma<<<dim3(MB * NH, NTOK / 64), 128, ATTN_SMEM>>>(qkh, qkl, ah, al);
        gemm_bf3<1><<<dim3(DMOD / BN, TOK / BM), 256, GEMM_SMEM>>>(
            BF16P(ah), BF16P(al), BF16P(wo_h), BF16P(wo_l),
            bo + l * DMOD, z, z, nullptr, nullptr, DMOD, DMOD);
        ln_kernel<<<TOK / 8, 256>>>(z, ln2_g + l * DMOD, ln2_b + l * DMOD, hh, hl);
        gemm_bf3<2><<<dim3(FFD / BN, TOK / BM), 256, GEMM_SMEM>>>(
            BF16P(hh), BF16P(hl), BF16P(f1_h), BF16P(f1_l),
            bff1 + l * FFD, nullptr, nullptr, fh, fl, DMOD, FFD);
        float* dst = (l == NLAY - 1) ? out : z;
        gemm_bf3<1><<<dim3(DMOD / BN, TOK / BM), 256, GEMM_SMEM>>>(
            BF16P(fh), BF16P(fl), BF16P(f2_h), BF16P(f2_l),
            bff2 + l * DMOD, z, dst, nullptr, nullptr, FFD, DMOD);
    }
}

// round 9
// speedup vs baseline: 3.2170x; 1.0583x over previous
#include <cuda_runtime.h>
#include <cuda_bf16.h>
#include <math.h>
#include <stdint.h>

// ---------------- problem constants ----------------
#define MB    8
#define NCC   512
#define NTOK  1024
#define DMOD  256
#define NH    8
#define NLAY  6
#define FFD   1024
#define DHD   32
#define TOK   (MB * NTOK)   // 8192

// ---------------- device scratch ----------------
__device__ float g_z[TOK * DMOD];
// split activations (bf16 hi/lo packed as uint32 pairs)
__device__ uint32_t g_h_h[TOK * DMOD / 2],  g_h_l[TOK * DMOD / 2];
__device__ uint32_t g_qkv_h[TOK * 3 * DMOD / 2], g_qkv_l[TOK * 3 * DMOD / 2];
__device__ uint32_t g_att_h[TOK * DMOD / 2], g_att_l[TOK * DMOD / 2];
__device__ uint32_t g_ff_h[TOK * FFD / 2],   g_ff_l[TOK * FFD / 2];
// split weights [K][N]
__device__ uint32_t g_wqkv_h[NLAY * DMOD * 3 * DMOD / 2], g_wqkv_l[NLAY * DMOD * 3 * DMOD / 2];
__device__ uint32_t g_wo_h[NLAY * DMOD * DMOD / 2],       g_wo_l[NLAY * DMOD * DMOD / 2];
__device__ uint32_t g_wff1_h[NLAY * DMOD * FFD / 2],      g_wff1_l[NLAY * DMOD * FFD / 2];
__device__ uint32_t g_wff2_h[NLAY * FFD * DMOD / 2],      g_wff2_l[NLAY * FFD * DMOD / 2];
__device__ uint32_t g_ew2_h[DMOD * DMOD / 2],             g_ew2_l[DMOD * DMOD / 2];

// ---------------- helpers ----------------
__device__ __forceinline__ void split2(float x0, float x1, uint32_t& h, uint32_t& l) {
    uint32_t hh;
    asm("cvt.rn.bf16x2.f32 %0, %1, %2;" : "=r"(hh) : "f"(x1), "f"(x0));
    float h0f = __uint_as_float(hh << 16);
    float h1f = __uint_as_float(hh & 0xffff0000u);
    h = hh;
    float l0 = x0 - h0f, l1 = x1 - h1f;
    asm("cvt.rn.bf16x2.f32 %0, %1, %2;" : "=r"(l) : "f"(l1), "f"(l0));
}
__device__ __forceinline__ float bflo(uint32_t v) { return __uint_as_float(v << 16); }
__device__ __forceinline__ float bfhi(uint32_t v) { return __uint_as_float(v & 0xffff0000u); }

__device__ __forceinline__ void cp_async16(void* dst, const void* src) {
    uint32_t d = (uint32_t)__cvta_generic_to_shared(dst);
    asm volatile("cp.async.cg.shared.global [%0], [%1], 16;\n" :: "r"(d), "l"(src));
}
__device__ __forceinline__ void cp_commit() { asm volatile("cp.async.commit_group;\n"); }
template <int N>
__device__ __forceinline__ void cp_wait() { asm volatile("cp.async.wait_group %0;\n" :: "n"(N)); }

__device__ __forceinline__ uint32_t smem_u32(const void* p) {
    return (uint32_t)__cvta_generic_to_shared(p);
}

#define LDM4(R0, R1, R2, R3, ADDR)                                          \
    asm volatile("ldmatrix.sync.aligned.m8n8.x4.shared.b16 {%0,%1,%2,%3}, [%4];" \
                 : "=r"(R0), "=r"(R1), "=r"(R2), "=r"(R3) : "r"(ADDR))

#define LDM4T(R0, R1, R2, R3, ADDR)                                         \
    asm volatile("ldmatrix.sync.aligned.m8n8.x4.trans.shared.b16 {%0,%1,%2,%3}, [%4];" \
                 : "=r"(R0), "=r"(R1), "=r"(R2), "=r"(R3) : "r"(ADDR))

#define MMA_BF16(ACC, A0, A1, A2, A3, B0, B1)                               \
    asm volatile(                                                           \
        "mma.sync.aligned.m16n8k16.row.col.f32.bf16.bf16.f32 "             \
        "{%0,%1,%2,%3}, {%4,%5,%6,%7}, {%8,%9}, {%0,%1,%2,%3};"            \
        : "+f"((ACC)[0]), "+f"((ACC)[1]), "+f"((ACC)[2]), "+f"((ACC)[3])   \
        : "r"(A0), "r"(A1), "r"(A2), "r"(A3), "r"(B0), "r"(B1))

// ---------------- weight split: fp32 -> bf16 hi/lo ----------------
__global__ void split_kernel(const float* __restrict__ src,
                             uint32_t* __restrict__ hi, uint32_t* __restrict__ lo,
                             int npairs)
{
    int i = blockIdx.x * 256 + threadIdx.x;
    if (i < npairs) {
        uint32_t h, l;
        split2(src[2 * i], src[2 * i + 1], h, l);
        hi[i] = h;
        lo[i] = l;
    }
}

// ---------------- pure-bf16 3-pass tensor-core GEMM (256 thr, 8 warps) ----------------
// BMV = 128 (warp tile 64x32, MI=4) or 64 (warp tile 32x32, MI=2; for N=256 gemms
// this doubles the grid to cover all 148 SMs with 2 CTAs/SM).
#define BN 128
#define BK 32
#define AST 40    // bf16 stride (80 B rows)
#define BST 136   // bf16 stride (272 B rows)
#define ASTB 80
#define BSTB 272
#define GEMM_SMEM(BMV) ((2*(BMV)*AST + 2*BK*BST) * 2 * 2)
// BMV=128: 75776 B ; BMV=64: 55296 B

// OUTMODE: 0 fp32, 1 fp32+resid, 2 relu+split, 3 split
template <int OUTMODE, int BMV>
__global__ __launch_bounds__(256) void gemm_bf3(
    const __nv_bfloat16* __restrict__ Ah, const __nv_bfloat16* __restrict__ Al,
    const __nv_bfloat16* __restrict__ Bh, const __nv_bfloat16* __restrict__ Bl,
    const float* __restrict__ bias, const float* __restrict__ Rsd,
    float* __restrict__ C, uint32_t* __restrict__ Chi, uint32_t* __restrict__ Clo,
    int K, int N)
{
    constexpr int MI = BMV / 32;          // m16 fragments per warp
    extern __shared__ char smem_raw[];
    __nv_bfloat16* sAh = (__nv_bfloat16*)smem_raw;
    __nv_bfloat16* sAl = sAh + 2 * BMV * AST;
    __nv_bfloat16* sBh = sAl + 2 * BMV * AST;
    __nv_bfloat16* sBl = sBh + 2 * BK * BST;

    const int tid = threadIdx.x;
    const int warp = tid >> 5, lane = tid & 31;
    const int g = lane >> 2, tg = lane & 3;
    const int wy = warp >> 2, wx = warp & 3;   // 2x4 warps
    const int row0 = blockIdx.y * BMV, col0 = blockIdx.x * BN;

    float acc[MI][4][4];
    #pragma unroll
    for (int a = 0; a < MI; a++)
        #pragma unroll
        for (int b = 0; b < 4; b++)
            #pragma unroll
            for (int c = 0; c < 4; c++) acc[a][b][c] = 0.0f;

    auto issue = [&](int t, int b) {
        #pragma unroll
        for (int s = tid; s < BMV * 4; s += 256) {
            int arow = s >> 2, aseg = s & 3;
            cp_async16(sAh + b * BMV * AST + arow * AST + aseg * 8,
                       Ah + (size_t)(row0 + arow) * K + t * BK + aseg * 8);
            cp_async16(sAl + b * BMV * AST + arow * AST + aseg * 8,
                       Al + (size_t)(row0 + arow) * K + t * BK + aseg * 8);
        }
        #pragma unroll
        for (int s = tid; s < 512; s += 256) {
            int brow = s >> 4, bseg = s & 15;
            cp_async16(sBh + b * BK * BST + brow * BST + bseg * 8,
                       Bh + (size_t)(t * BK + brow) * N + col0 + bseg * 8);
            cp_async16(sBl + b * BK * BST + brow * BST + bseg * 8,
                       Bl + (size_t)(t * BK + brow) * N + col0 + bseg * 8);
        }
        cp_commit();
    };

    const int a_lane = (wy * (BMV / 2) + (lane & 15)) * ASTB + (lane >> 4) * 16;
    const int b_lane = (lane & 15) * BSTB + (lane >> 4) * 16 + wx * 64;

    auto compute = [&](int b) {
        uint32_t aHb = smem_u32(sAh + b * BMV * AST) + a_lane;
        uint32_t aLb = smem_u32(sAl + b * BMV * AST) + a_lane;
        uint32_t bHb = smem_u32(sBh + b * BK * BST) + b_lane;
        uint32_t bLb = smem_u32(sBl + b * BK * BST) + b_lane;

        #pragma unroll
        for (int ks = 0; ks < 2; ks++) {
            uint32_t ah[MI][4], al[MI][4], bh[2][4], bl[2][4];
            #pragma unroll
            for (int mi = 0; mi < MI; mi++) {
                LDM4(ah[mi][0], ah[mi][1], ah[mi][2], ah[mi][3],
                     aHb + mi * 16 * ASTB + ks * 32);
                LDM4(al[mi][0], al[mi][1], al[mi][2], al[mi][3],
                     aLb + mi * 16 * ASTB + ks * 32);
            }
            #pragma unroll
            for (int nc = 0; nc < 2; nc++) {
                LDM4T(bh[nc][0], bh[nc][1], bh[nc][2], bh[nc][3],
                      bHb + ks * 16 * BSTB + nc * 32);
                LDM4T(bl[nc][0], bl[nc][1], bl[nc][2], bl[nc][3],
                      bLb + ks * 16 * BSTB + nc * 32);
            }
            #pragma unroll
            for (int mi = 0; mi < MI; mi++)
                #pragma unroll
                for (int nf = 0; nf < 4; nf++) {
                    const int p = nf >> 1, q = (nf & 1) * 2;
                    MMA_BF16(acc[mi][nf], al[mi][0], al[mi][1], al[mi][2], al[mi][3],
                             bh[p][q], bh[p][q + 1]);
                    MMA_BF16(acc[mi][nf], ah[mi][0], ah[mi][1], ah[mi][2], ah[mi][3],
                             bl[p][q], bl[p][q + 1]);
                    MMA_BF16(acc[mi][nf], ah[mi][0], ah[mi][1], ah[mi][2], ah[mi][3],
                             bh[p][q], bh[p][q + 1]);
                }
        }
    };

    const int T = K / BK;
    issue(0, 0);
    for (int t = 0; t < T; t++) {
        const int buf = t & 1;
        if (t + 1 < T) {
            issue(t + 1, buf ^ 1);
            cp_wait<1>();
        } else {
            cp_wait<0>();
        }
        __syncthreads();
        compute(buf);
        __syncthreads();
    }

    #pragma unroll
    for (int mi = 0; mi < MI; mi++) {
        #pragma unroll
        for (int nf = 0; nf < 4; nf++) {
            const int r = row0 + wy * (BMV / 2) + mi * 16 + g;
            const int c = col0 + wx * 32 + nf * 8 + tg * 2;
            const float b0 = bias[c], b1 = bias[c + 1];
            float v0 = acc[mi][nf][0] + b0;
            float v1 = acc[mi][nf][1] + b1;
            float v2 = acc[mi][nf][2] + b0;
            float v3 = acc[mi][nf][3] + b1;
            if (OUTMODE >= 2) {
                if (OUTMODE == 2) {
                    v0 = fmaxf(v0, 0.0f); v1 = fmaxf(v1, 0.0f);
                    v2 = fmaxf(v2, 0.0f); v3 = fmaxf(v3, 0.0f);
                }
                uint32_t h, l;
                split2(v0, v1, h, l);
                Chi[((size_t)r * N + c) >> 1] = h;
                Clo[((size_t)r * N + c) >> 1] = l;
                split2(v2, v3, h, l);
                Chi[((size_t)(r + 8) * N + c) >> 1] = h;
                Clo[((size_t)(r + 8) * N + c) >> 1] = l;
            } else {
                if (OUTMODE == 1) {
                    v0 += Rsd[(size_t)r * N + c];
                    v1 += Rsd[(size_t)r * N + c + 1];
                    v2 += Rsd[(size_t)(r + 8) * N + c];
                    v3 += Rsd[(size_t)(r + 8) * N + c + 1];
                }
                *(float2*)&C[(size_t)r * N + c]       = make_float2(v0, v1);
                *(float2*)&C[(size_t)(r + 8) * N + c] = make_float2(v2, v3);
            }
        }
    }
}

// ---------------- tensor-core flash attention (R7, unchanged) ----------------
#define QST 40
#define QSTB 80
#define ATTN_SMEM ((2*64*QST + 8*64*QST) * 2)   // 51200 bytes

__global__ __launch_bounds__(128) void attn_mma(
    const uint32_t* __restrict__ qh, const uint32_t* __restrict__ ql,
    uint32_t* __restrict__ oh, uint32_t* __restrict__ ol)
{
    extern __shared__ char sm[];
    __nv_bfloat16* sQh = (__nv_bfloat16*)sm;
    __nv_bfloat16* sQl = sQh + 64 * QST;
    __nv_bfloat16* sKh = sQl + 64 * QST;
    __nv_bfloat16* sKl = sKh + 2 * 64 * QST;
    __nv_bfloat16* sVh = sKl + 2 * 64 * QST;
    __nv_bfloat16* sVl = sVh + 2 * 64 * QST;

    const int mh = blockIdx.x, qb = blockIdx.y;
    const int m = mh >> 3, h = mh & 7;
    const int q0 = qb * 64;
    const int tid = threadIdx.x, warp = tid >> 5, lane = tid & 31;
    const int g = lane >> 2, tg = lane & 3;
    const int tb = m * NTOK;
    const float scale = 0.17677669529663687f;

    const int i0 = tid * 2;
    const int lrow0 = i0 >> 2, lseg0 = i0 & 3;
    const int lrow1 = (i0 + 1) >> 2, lseg1 = (i0 + 1) & 3;

    {
        size_t s0 = (size_t)(tb + q0 + lrow0) * 384 + h * 16 + lseg0 * 4;
        size_t s1 = (size_t)(tb + q0 + lrow1) * 384 + h * 16 + lseg1 * 4;
        cp_async16(sQh + lrow0 * QST + lseg0 * 8, qh + s0);
        cp_async16(sQh + lrow1 * QST + lseg1 * 8, qh + s1);
        cp_async16(sQl + lrow0 * QST + lseg0 * 8, ql + s0);
        cp_async16(sQl + lrow1 * QST + lseg1 * 8, ql + s1);
        cp_commit();
    }
    auto issueKV = [&](int c, int b) {
        int k0 = c * 64;
        size_t s0 = (size_t)(tb + k0 + lrow0) * 384 + 128 + h * 16 + lseg0 * 4;
        size_t s1 = (size_t)(tb + k0 + lrow1) * 384 + 128 + h * 16 + lseg1 * 4;
        __nv_bfloat16* kh = sKh + b * 64 * QST;
        __nv_bfloat16* kl = sKl + b * 64 * QST;
        __nv_bfloat16* vh = sVh + b * 64 * QST;
        __nv_bfloat16* vl = sVl + b * 64 * QST;
        cp_async16(kh + lrow0 * QST + lseg0 * 8, qh + s0);
        cp_async16(kh + lrow1 * QST + lseg1 * 8, qh + s1);
        cp_async16(kl + lrow0 * QST + lseg0 * 8, ql + s0);
        cp_async16(kl + lrow1 * QST + lseg1 * 8, ql + s1);
        cp_async16(vh + lrow0 * QST + lseg0 * 8, qh + s0 + 128);
        cp_async16(vh + lrow1 * QST + lseg1 * 8, qh + s1 + 128);
        cp_async16(vl + lrow0 * QST + lseg0 * 8, ql + s0 + 128);
        cp_async16(vl + lrow1 * QST + lseg1 * 8, ql + s1 + 128);
        cp_commit();
    };

    issueKV(0, 0);
    cp_wait<1>();
    __syncthreads();

    uint32_t qfh[2][4], qfl[2][4];
    {
        uint32_t bh_ = smem_u32(sQh) + (warp * 16 + (lane & 15)) * QSTB + (lane >> 4) * 16;
        uint32_t bl_ = smem_u32(sQl) + (warp * 16 + (lane & 15)) * QSTB + (lane >> 4) * 16;
        LDM4(qfh[0][0], qfh[0][1], qfh[0][2], qfh[0][3], bh_);
        LDM4(qfh[1][0], qfh[1][1], qfh[1][2], qfh[1][3], bh_ + 32);
        LDM4(qfl[0][0], qfl[0][1], qfl[0][2], qfl[0][3], bl_);
        LDM4(qfl[1][0], qfl[1][1], qfl[1][2], qfl[1][3], bl_ + 32);
    }

    float mx0 = -1e30f, mx1 = -1e30f, sum0 = 0.f, sum1 = 0.f;
    float oacc[4][4];
    #pragma unroll
    for (int a = 0; a < 4; a++)
        #pragma unroll
        for (int b = 0; b < 4; b++) oacc[a][b] = 0.f;

    const uint32_t kbyte = ((lane & 7) + ((lane >> 4) & 1) * 8) * QSTB +
                           ((lane >> 3) & 1) * 16;
    const uint32_t vbyte = (lane & 15) * QSTB + (lane >> 4) * 16;

    for (int c = 0; c < 8; c++) {
        const int b = c & 1;
        if (c + 1 < 8) { issueKV(c + 1, b ^ 1); cp_wait<1>(); }
        else           { cp_wait<0>(); }
        __syncthreads();

        uint32_t khb = smem_u32(sKh + b * 64 * QST) + kbyte;
        uint32_t klb = smem_u32(sKl + b * 64 * QST) + kbyte;

        float sacc[8][4];
        #pragma unroll
        for (int a = 0; a < 8; a++)
            #pragma unroll
            for (int j = 0; j < 4; j++) sacc[a][j] = 0.f;

        #pragma unroll
        for (int nk = 0; nk < 4; nk++) {
            uint32_t kh0[4], kh1[4], kl0[4], kl1[4];
            LDM4(kh0[0], kh0[1], kh0[2], kh0[3], khb + nk * 16 * QSTB);
            LDM4(kh1[0], kh1[1], kh1[2], kh1[3], khb + nk * 16 * QSTB + 32);
            LDM4(kl0[0], kl0[1], kl0[2], kl0[3], klb + nk * 16 * QSTB);
            LDM4(kl1[0], kl1[1], kl1[2], kl1[3], klb + nk * 16 * QSTB + 32);
            MMA_BF16(sacc[nk*2], qfl[0][0], qfl[0][1], qfl[0][2], qfl[0][3], kh0[0], kh0[1]);
            MMA_BF16(sacc[nk*2], qfl[1][0], qfl[1][1], qfl[1][2], qfl[1][3], kh1[0], kh1[1]);
            MMA_BF16(sacc[nk*2], qfh[0][0], qfh[0][1], qfh[0][2], qfh[0][3], kl0[0], kl0[1]);
            MMA_BF16(sacc[nk*2], qfh[1][0], qfh[1][1], qfh[1][2], qfh[1][3], kl1[0], kl1[1]);
            MMA_BF16(sacc[nk*2], qfh[0][0], qfh[0][1], qfh[0][2], qfh[0][3], kh0[0], kh0[1]);
            MMA_BF16(sacc[nk*2], qfh[1][0], qfh[1][1], qfh[1][2], qfh[1][3], kh1[0], kh1[1]);
            MMA_BF16(sacc[nk*2+1], qfl[0][0], qfl[0][1], qfl[0][2], qfl[0][3], kh0[2], kh0[3]);
            MMA_BF16(sacc[nk*2+1], qfl[1][0], qfl[1][1], qfl[1][2], qfl[1][3], kh1[2], kh1[3]);
            MMA_BF16(sacc[nk*2+1], qfh[0][0], qfh[0][1], qfh[0][2], qfh[0][3], kl0[2], kl0[3]);
            MMA_BF16(sacc[nk*2+1], qfh[1][0], qfh[1][1], qfh[1][2], qfh[1][3], kl1[2], kl1[3]);
            MMA_BF16(sacc[nk*2+1], qfh[0][0], qfh[0][1], qfh[0][2], qfh[0][3], kh0[2], kh0[3]);
            MMA_BF16(sacc[nk*2+1], qfh[1][0], qfh[1][1], qfh[1][2], qfh[1][3], kh1[2], kh1[3]);
        }

        float cm0 = -1e30f, cm1 = -1e30f;
        #pragma unroll
        for (int a = 0; a < 8; a++) {
            #pragma unroll
            for (int j = 0; j < 4; j++) sacc[a][j] *= scale;
            cm0 = fmaxf(cm0, fmaxf(sacc[a][0], sacc[a][1]));
            cm1 = fmaxf(cm1, fmaxf(sacc[a][2], sacc[a][3]));
        }
        cm0 = fmaxf(cm0, __shfl_xor_sync(~0u, cm0, 1));
        cm0 = fmaxf(cm0, __shfl_xor_sync(~0u, cm0, 2));
        cm1 = fmaxf(cm1, __shfl_xor_sync(~0u, cm1, 1));
        cm1 = fmaxf(cm1, __shfl_xor_sync(~0u, cm1, 2));
        float nm0 = fmaxf(mx0, cm0), nm1 = fmaxf(mx1, cm1);
        float c0 = __expf(mx0 - nm0), c1 = __expf(mx1 - nm1);
        sum0 *= c0; sum1 *= c1;
        #pragma unroll
        for (int a = 0; a < 4; a++) {
            oacc[a][0] *= c0; oacc[a][1] *= c0;
            oacc[a][2] *= c1; oacc[a][3] *= c1;
        }
        #pragma unroll
        for (int a = 0; a < 8; a++) {
            sacc[a][0] = __expf(sacc[a][0] - nm0);
            sacc[a][1] = __expf(sacc[a][1] - nm0);
            sacc[a][2] = __expf(sacc[a][2] - nm1);
            sacc[a][3] = __expf(sacc[a][3] - nm1);
            sum0 += sacc[a][0] + sacc[a][1];
            sum1 += sacc[a][2] + sacc[a][3];
        }
        mx0 = nm0; mx1 = nm1;

        uint32_t pah[4][4], pal[4][4];
        #pragma unroll
        for (int kf = 0; kf < 4; kf++) {
            split2(sacc[kf*2][0],   sacc[kf*2][1],   pah[kf][0], pal[kf][0]);
            split2(sacc[kf*2][2],   sacc[kf*2][3],   pah[kf][1], pal[kf][1]);
            split2(sacc[kf*2+1][0], sacc[kf*2+1][1], pah[kf][2], pal[kf][2]);
            split2(sacc[kf*2+1][2], sacc[kf*2+1][3], pah[kf][3], pal[kf][3]);
        }

        uint32_t vhb = smem_u32(sVh + b * 64 * QST) + vbyte;
        uint32_t vlb = smem_u32(sVl + b * 64 * QST) + vbyte;
        #pragma unroll
        for (int nc = 0; nc < 2; nc++) {
            #pragma unroll
            for (int kf = 0; kf < 4; kf++) {
                uint32_t vh_[4], vl_[4];
                LDM4T(vh_[0], vh_[1], vh_[2], vh_[3], vhb + kf * 16 * QSTB + nc * 32);
                LDM4T(vl_[0], vl_[1], vl_[2], vl_[3], vlb + kf * 16 * QSTB + nc * 32);
                MMA_BF16(oacc[nc*2], pal[kf][0], pal[kf][1], pal[kf][2], pal[kf][3], vh_[0], vh_[1]);
                MMA_BF16(oacc[nc*2], pah[kf][0], pah[kf][1], pah[kf][2], pah[kf][3], vl_[0], vl_[1]);
                MMA_BF16(oacc[nc*2], pah[kf][0], pah[kf][1], pah[kf][2], pah[kf][3], vh_[0], vh_[1]);
                MMA_BF16(oacc[nc*2+1], pal[kf][0], pal[kf][1], pal[kf][2], pal[kf][3], vh_[2], vh_[3]);
                MMA_BF16(oacc[nc*2+1], pah[kf][0], pah[kf][1], pah[kf][2], pah[kf][3], vl_[2], vl_[3]);
                MMA_BF16(oacc[nc*2+1], pah[kf][0], pah[kf][1], pah[kf][2], pah[kf][3], vh_[2], vh_[3]);
            }
        }
        __syncthreads();
    }

    if (q0 >= NCC) {
        #pragma unroll
        for (int half = 0; half < 2; half++) {
            int row = q0 + warp * 16 + g + half * 8;
            size_t pb = (size_t)(tb + row) * 384;
            float dot = 0.f;
            #pragma unroll
            for (int w = 0; w < 4; w++) {
                uint32_t qhv = qh[pb + h * 16 + tg * 4 + w];
                uint32_t qlv = ql[pb + h * 16 + tg * 4 + w];
                uint32_t khv = qh[pb + 128 + h * 16 + tg * 4 + w];
                uint32_t klv = ql[pb + 128 + h * 16 + tg * 4 + w];
                float qa = bflo(qhv) + bflo(qlv), qb_ = bfhi(qhv) + bfhi(qlv);
                float ka = bflo(khv) + bflo(klv), kb = bfhi(khv) + bfhi(klv);
                dot += qa * ka + qb_ * kb;
            }
            dot += __shfl_xor_sync(~0u, dot, 1);
            dot += __shfl_xor_sync(~0u, dot, 2);
            float s = dot * scale;
            float mxv = half ? mx1 : mx0;
            float nm = fmaxf(mxv, s);
            float corr = __expf(mxv - nm);
            float p = __expf(s - nm);
            if (half) { sum1 = sum1 * corr + (tg == 0 ? p : 0.f); mx1 = nm; }
            else      { sum0 = sum0 * corr + (tg == 0 ? p : 0.f); mx0 = nm; }
            #pragma unroll
            for (int nf = 0; nf < 4; nf++) {
                uint32_t vhv = qh[pb + 256 + h * 16 + nf * 4 + tg];
                uint32_t vlv = ql[pb + 256 + h * 16 + nf * 4 + tg];
                float v0 = bflo(vhv) + bflo(vlv);
                float v1 = bfhi(vhv) + bfhi(vlv);
                oacc[nf][half*2]   = oacc[nf][half*2]   * corr + p * v0;
                oacc[nf][half*2+1] = oacc[nf][half*2+1] * corr + p * v1;
            }
        }
    }

    sum0 += __shfl_xor_sync(~0u, sum0, 1);
    sum0 += __shfl_xor_sync(~0u, sum0, 2);
    sum1 += __shfl_xor_sync(~0u, sum1, 1);
    sum1 += __shfl_xor_sync(~0u, sum1, 2);
    float inv0 = 1.f / sum0, inv1 = 1.f / sum1;

    int row = q0 + warp * 16 + g;
    size_t ob0 = ((size_t)(tb + row) * 256 + h * 32) >> 1;
    size_t ob1 = ((size_t)(tb + row + 8) * 256 + h * 32) >> 1;
    #pragma unroll
    for (int nf = 0; nf < 4; nf++) {
        uint32_t hh_, ll_;
        split2(oacc[nf][0] * inv0, oacc[nf][1] * inv0, hh_, ll_);
        oh[ob0 + nf * 4 + tg] = hh_;
        ol[ob0 + nf * 4 + tg] = ll_;
        split2(oacc[nf][2] * inv1, oacc[nf][3] * inv1, hh_, ll_);
        oh[ob1 + nf * 4 + tg] = hh_;
        ol[ob1 + nf * 4 + tg] = ll_;
    }
}

// ---------------- encoder layer-1 ----------------
__global__ __launch_bounds__(128) void encode_hidden(
    const float* __restrict__ xc, const float* __restrict__ yc,
    const float* __restrict__ xt,
    const float* __restrict__ W1, const float* __restrict__ b1,
    uint32_t* __restrict__ hh, uint32_t* __restrict__ hl)
{
    int tok = blockIdx.x;
    int m = tok >> 10, t = tok & 1023;
    int tid = threadIdx.x;
    int d = tid * 2;

    __shared__ float s_in[16];
    if (tid < 10) {
        float v;
        if (tid < 8) {
            v = (t < NCC) ? xc[(m * NCC + t) * 8 + tid]
                          : xt[(m * NCC + (t - NCC)) * 8 + tid];
        } else if (tid == 8) {
            v = (t < NCC) ? yc[m * NCC + t] : 0.0f;
        } else {
            v = (t < NCC) ? 0.0f : 1.0f;
        }
        s_in[tid] = v;
    }
    __syncthreads();

    float a0 = b1[d], a1 = b1[d + 1];
    #pragma unroll
    for (int k = 0; k < 10; k++) {
        a0 += s_in[k] * W1[k * DMOD + d];
        a1 += s_in[k] * W1[k * DMOD + d + 1];
    }
    uint32_t h, l;
    split2(fmaxf(a0, 0.0f), fmaxf(a1, 0.0f), h, l);
    hh[tok * 128 + tid] = h;
    hl[tok * 128 + tid] = l;
}

// ---------------- layernorm (warp/token), split bf16 output ----------------
__global__ __launch_bounds__(256) void ln_kernel(
    const float* __restrict__ x, const float* __restrict__ g,
    const float* __restrict__ b,
    uint32_t* __restrict__ yh, uint32_t* __restrict__ yl)
{
    int tok  = (blockIdx.x * 256 + threadIdx.x) >> 5;
    int lane = threadIdx.x & 31;

    const float4* xp = (const float4*)(x + (size_t)tok * DMOD);
    float4 v0 = xp[lane * 2], v1 = xp[lane * 2 + 1];

    float s = v0.x + v0.y + v0.z + v0.w + v1.x + v1.y + v1.z + v1.w;
    #pragma unroll
    for (int o = 16; o > 0; o >>= 1) s += __shfl_xor_sync(0xffffffffu, s, o);
    float mu = s * (1.0f / DMOD);

    float d0 = v0.x - mu, d1 = v0.y - mu, d2 = v0.z - mu, d3 = v0.w - mu;
    float d4 = v1.x - mu, d5 = v1.y - mu, d6 = v1.z - mu, d7 = v1.w - mu;
    float q = d0*d0 + d1*d1 + d2*d2 + d3*d3 + d4*d4 + d5*d5 + d6*d6 + d7*d7;
    #pragma unroll
    for (int o = 16; o > 0; o >>= 1) q += __shfl_xor_sync(0xffffffffu, q, o);
    float rstd = rsqrtf(q * (1.0f / DMOD) + 1e-5f);

    const float4* gp = (const float4*)g;
    const float4* bp = (const float4*)b;
    float4 g0 = gp[lane * 2], g1 = gp[lane * 2 + 1];
    float4 b0 = bp[lane * 2], b1 = bp[lane * 2 + 1];

    float o0 = d0 * rstd * g0.x + b0.x, o1 = d1 * rstd * g0.y + b0.y;
    float o2 = d2 * rstd * g0.z + b0.z, o3 = d3 * rstd * g0.w + b0.w;
    float o4 = d4 * rstd * g1.x + b1.x, o5 = d5 * rstd * g1.y + b1.y;
    float o6 = d6 * rstd * g1.z + b1.z, o7 = d7 * rstd * g1.w + b1.w;

    uint32_t h, l;
    int base = tok * 128 + lane * 4;
    split2(o0, o1, h, l);  yh[base + 0] = h;  yl[base + 0] = l;
    split2(o2, o3, h, l);  yh[base + 1] = h;  yl[base + 1] = l;
    split2(o4, o5, h, l);  yh[base + 2] = h;  yl[base + 2] = l;
    split2(o6, o7, h, l);  yh[base + 3] = h;  yl[base + 3] = l;
}

// ---------------- launch ----------------
#define BF16P(sym) ((const __nv_bfloat16*)sym)

extern "C" void kernel_launch(void* const* d_in, const int* in_sizes, int n_in,
                              void* d_out, int out_size)
{
    const float* xc     = (const float*)d_in[0];
    const float* yc     = (const float*)d_in[1];
    const float* xt     = (const float*)d_in[2];
    const float* enc_W1 = (const float*)d_in[3];
    const float* enc_b1 = (const float*)d_in[4];
    const float* enc_W2 = (const float*)d_in[5];
    const float* enc_b2 = (const float*)d_in[6];
    const float* Wqkv   = (const float*)d_in[7];
    const float* bqkv   = (const float*)d_in[8];
    const float* Wo     = (const float*)d_in[9];
    const float* bo     = (const float*)d_in[10];
    const float* ln1_g  = (const float*)d_in[11];
    const float* ln1_b  = (const float*)d_in[12];
    const float* ln2_g  = (const float*)d_in[13];
    const float* ln2_b  = (const float*)d_in[14];
    const float* Wff1   = (const float*)d_in[15];
    const float* bff1   = (const float*)d_in[16];
    const float* Wff2   = (const float*)d_in[17];
    const float* bff2   = (const float*)d_in[18];
    float* out          = (float*)d_out;

    float* z;
    uint32_t *hh, *hl, *qkh, *qkl, *ah, *al, *fh, *fl;
    uint32_t *wqh, *wql, *woh, *wol, *w1h, *w1l, *w2h, *w2l, *ewh, *ewl;
    cudaGetSymbolAddress((void**)&z,   g_z);
    cudaGetSymbolAddress((void**)&hh,  g_h_h);   cudaGetSymbolAddress((void**)&hl,  g_h_l);
    cudaGetSymbolAddress((void**)&qkh, g_qkv_h); cudaGetSymbolAddress((void**)&qkl, g_qkv_l);
    cudaGetSymbolAddress((void**)&ah,  g_att_h); cudaGetSymbolAddress((void**)&al,  g_att_l);
    cudaGetSymbolAddress((void**)&fh,  g_ff_h);  cudaGetSymbolAddress((void**)&fl,  g_ff_l);
    cudaGetSymbolAddress((void**)&wqh, g_wqkv_h); cudaGetSymbolAddress((void**)&wql, g_wqkv_l);
    cudaGetSymbolAddress((void**)&woh, g_wo_h);   cudaGetSymbolAddress((void**)&wol, g_wo_l);
    cudaGetSymbolAddress((void**)&w1h, g_wff1_h); cudaGetSymbolAddress((void**)&w1l, g_wff1_l);
    cudaGetSymbolAddress((void**)&w2h, g_wff2_h); cudaGetSymbolAddress((void**)&w2l, g_wff2_l);
    cudaGetSymbolAddress((void**)&ewh, g_ew2_h);  cudaGetSymbolAddress((void**)&ewl, g_ew2_l);

    const int SM128 = GEMM_SMEM(128);
    const int SM64  = GEMM_SMEM(64);
    cudaFuncSetAttribute(gemm_bf3<0, 64>,  cudaFuncAttributeMaxDynamicSharedMemorySize, SM64);
    cudaFuncSetAttribute(gemm_bf3<1, 64>,  cudaFuncAttributeMaxDynamicSharedMemorySize, SM64);
    cudaFuncSetAttribute(gemm_bf3<2, 128>, cudaFuncAttributeMaxDynamicSharedMemorySize, SM128);
    cudaFuncSetAttribute(gemm_bf3<3, 128>, cudaFuncAttributeMaxDynamicSharedMemorySize, SM128);
    cudaFuncSetAttribute(attn_mma, cudaFuncAttributeMaxDynamicSharedMemorySize, ATTN_SMEM);

    auto splitw = [&](const float* src, uint32_t* hi, uint32_t* lo, int npairs) {
        split_kernel<<<(npairs + 255) / 256, 256>>>(src, hi, lo, npairs);
    };
    splitw(enc_W2, ewh, ewl, DMOD * DMOD / 2);
    splitw(Wqkv,   wqh, wql, NLAY * DMOD * 3 * DMOD / 2);
    splitw(Wo,     woh, wol, NLAY * DMOD * DMOD / 2);
    splitw(Wff1,   w1h, w1l, NLAY * DMOD * FFD / 2);
    splitw(Wff2,   w2h, w2l, NLAY * FFD * DMOD / 2);

    encode_hidden<<<TOK, 128>>>(xc, yc, xt, enc_W1, enc_b1, hh, hl);
    gemm_bf3<0, 64><<<dim3(DMOD / BN, TOK / 64), 256, SM64>>>(
        BF16P(hh), BF16P(hl), BF16P(ewh), BF16P(ewl),
        enc_b2, nullptr, z, nullptr, nullptr, DMOD, DMOD);

    for (int l = 0; l < NLAY; l++) {
        const uint32_t* wq_h = wqh + (size_t)l * DMOD * 3 * DMOD / 2;
        const uint32_t* wq_l = wql + (size_t)l * DMOD * 3 * DMOD / 2;
        const uint32_t* wo_h = woh + (size_t)l * DMOD * DMOD / 2;
        const uint32_t* wo_l = wol + (size_t)l * DMOD * DMOD / 2;
        const uint32_t* f1_h = w1h + (size_t)l * DMOD * FFD / 2;
        const uint32_t* f1_l = w1l + (size_t)l * DMOD * FFD / 2;
        const uint32_t* f2_h = w2h + (size_t)l * FFD * DMOD / 2;
        const uint32_t* f2_l = w2l + (size_t)l * FFD * DMOD / 2;

        ln_kernel<<<TOK / 8, 256>>>(z, ln1_g + l * DMOD, ln1_b + l * DMOD, hh, hl);
        gemm_bf3<3, 128><<<dim3(3 * DMOD / BN, TOK / 128), 256, SM128>>>(
            BF16P(hh), BF16P(hl), BF16P(wq_h), BF16P(wq_l),
            bqkv + l * 3 * DMOD, nullptr, nullptr, qkh, qkl, DMOD, 3 * DMOD);
        attn_mma<<<dim3(MB * NH, NTOK / 64), 128, ATTN_SMEM>>>(qkh, qkl, ah, al);
        gemm_bf3<1, 64><<<dim3(DMOD / BN, TOK / 64), 256, SM64>>>(
            BF16P(ah), BF16P(al), BF16P(wo_h), BF16P(wo_l),
            bo + l * DMOD, z, z, nullptr, nullptr, DMOD, DMOD);
        ln_kernel<<<TOK / 8, 256>>>(z, ln2_g + l * DMOD, ln2_b + l * DMOD, hh, hl);
        gemm_bf3<2, 128><<<dim3(FFD / BN, TOK / 128), 256, SM128>>>(
            BF16P(hh), BF16P(hl), BF16P(f1_h), BF16P(f1_l),
            bff1 + l * FFD, nullptr, nullptr, fh, fl, DMOD, FFD);
        float* dst = (l == NLAY - 1) ? out : z;
        gemm_bf3<1, 64><<<dim3(DMOD / BN, TOK / 64), 256, SM64>>>(
            BF16P(fh), BF16P(fl), BF16P(f2_h), BF16P(f2_l),
            bff2 + l * DMOD, z, dst, nullptr, nullptr, FFD, DMOD);
    }
}